// round 9
// baseline (speedup 1.0000x reference)
#include <cuda_runtime.h>
#include <cuda_fp16.h>
#include <cstdint>

// AdaMoeLayer: out[t] = sum_e w[t,e]*(x[t] @ W_e + b_e),  T=32768, D=512, E=8.
// fp16 mma.sync m16n8k16, X split hi/lo, W fp16. R9: stage = k16 chunk with
// ALL experts' B tiles; A fragments loaded once per stage and reused across
// the 8 experts (LDS/MMA cut 3x vs R8). Warp tile 32x32, CTA 128x64.

#define D_DIM 512
#define E_DIM 8
#define T_TOK 32768
#define MAX_THRESHOLD 0.25f

// ---- static device scratch ----
__device__ float g_w[T_TOK * E_DIM];                       // gate weights, 1 MB
__device__ __half g_Wh[(size_t)E_DIM * D_DIM * D_DIM];     // fp16 W' [e][n][k-perm], 4 MB
__device__ __half g_Xh[(size_t)T_TOK * D_DIM];             // fp16 X hi [t][k-perm], 32 MB
__device__ __half g_Xl[(size_t)T_TOK * D_DIM];             // fp16 X lo [t][k-perm], 32 MB

// ---------------------------------------------------------------------------
__device__ __forceinline__ uint32_t smem_u32(const void* p) {
    uint32_t a;
    asm("{ .reg .u64 t; cvta.to.shared.u64 t, %1; cvt.u32.u64 %0, t; }"
        : "=r"(a) : "l"(p));
    return a;
}
__device__ __forceinline__ void cp16(uint32_t dst, const void* src) {
    asm volatile("cp.async.cg.shared.global [%0], [%1], 16;\n"
                 :: "r"(dst), "l"(__cvta_generic_to_global(src)) : "memory");
}
__device__ __forceinline__ void mma_f16(float* c,
    uint32_t a0, uint32_t a1, uint32_t a2, uint32_t a3,
    uint32_t b0, uint32_t b1)
{
    asm volatile(
        "mma.sync.aligned.m16n8k16.row.col.f32.f16.f16.f32 "
        "{%0,%1,%2,%3}, {%4,%5,%6,%7}, {%8,%9}, {%0,%1,%2,%3};"
        : "+f"(c[0]), "+f"(c[1]), "+f"(c[2]), "+f"(c[3])
        : "r"(a0), "r"(a1), "r"(a2), "r"(a3), "r"(b0), "r"(b1));
}

// ---------------------------------------------------------------------------
// Kernel 1: gating. One warp per token.
// ---------------------------------------------------------------------------
__global__ __launch_bounds__(256) void gating_kernel(
    const float* __restrict__ x,
    const float* __restrict__ Wg, const float* __restrict__ bg,
    const float* __restrict__ Wt, const float* __restrict__ bt)
{
    __shared__ float sWg[E_DIM][D_DIM];
    __shared__ float sWt[D_DIM];
    const int tid = threadIdx.x;
    for (int i = tid; i < E_DIM * D_DIM; i += 256) {
        int e = i / D_DIM, d = i - e * D_DIM;
        sWg[e][d] = Wg[d * E_DIM + e];
    }
    for (int i = tid; i < D_DIM; i += 256) sWt[i] = Wt[i];
    __syncthreads();

    const int warp = tid >> 5, lane = tid & 31;
    const int t = blockIdx.x * 8 + warp;
    const float* xr = x + (size_t)t * D_DIM;

    float acc[9];
#pragma unroll
    for (int e = 0; e < 9; e++) acc[e] = 0.f;
#pragma unroll
    for (int i = 0; i < D_DIM / 32; i++) {
        int d = lane + 32 * i;
        float xv = xr[d];
#pragma unroll
        for (int e = 0; e < E_DIM; e++) acc[e] = fmaf(xv, sWg[e][d], acc[e]);
        acc[8] = fmaf(xv, sWt[d], acc[8]);
    }
#pragma unroll
    for (int off = 16; off > 0; off >>= 1)
#pragma unroll
        for (int e = 0; e < 9; e++) acc[e] += __shfl_xor_sync(0xffffffffu, acc[e], off);

    float logit[E_DIM];
#pragma unroll
    for (int e = 0; e < E_DIM; e++) logit[e] = acc[e] + bg[e];
    float m = logit[0];
#pragma unroll
    for (int e = 1; e < E_DIM; e++) m = fmaxf(m, logit[e]);
    float p[E_DIM], s = 0.f;
#pragma unroll
    for (int e = 0; e < E_DIM; e++) { p[e] = expf(logit[e] - m); s += p[e]; }
    float inv_s = 1.f / s;
    float thr = (1.f / (1.f + expf(-(acc[8] + bt[0])))) * MAX_THRESHOLD;

    float w[E_DIM], ws = 0.f;
#pragma unroll
    for (int e = 0; e < E_DIM; e++) {
        float a = p[e] * inv_s - thr;
        w[e] = (a >= 0.f) ? a : 0.f;
        ws += w[e];
    }
    if (ws == 0.f) ws = 1.f;
    float inv_ws = 1.f / ws;

    if (lane < E_DIM) {
        float v = 0.f;
#pragma unroll
        for (int e = 0; e < E_DIM; e++) if (lane == e) v = w[e];
        g_w[t * E_DIM + lane] = v * inv_ws;
    }
}

// ---------------------------------------------------------------------------
// Kernel 2a: X -> fp16 hi/lo, pair-permuted within each 16-k group.
// Pair p (0..7) stored at u32 slot s(p) = p<4 ? 2p : 2(p-4)+1.
// ---------------------------------------------------------------------------
__global__ __launch_bounds__(256) void xprep_kernel(const float* __restrict__ X)
{
    size_t idx = (size_t)blockIdx.x * 256 + threadIdx.x;
    size_t base = idx * 16;
    float v[16];
#pragma unroll
    for (int i = 0; i < 4; i++)
        *reinterpret_cast<float4*>(v + i * 4) =
            *reinterpret_cast<const float4*>(X + base + i * 4);

    uint32_t oh[8], ol[8];
#pragma unroll
    for (int p = 0; p < 8; p++) {
        float v0 = v[2 * p], v1 = v[2 * p + 1];
        __half h0 = __float2half(v0), h1 = __float2half(v1);
        __half l0 = __float2half(v0 - __half2float(h0));
        __half l1 = __float2half(v1 - __half2float(h1));
        int s = (p < 4) ? 2 * p : 2 * (p - 4) + 1;
        __half2 ph; ph.x = h0; ph.y = h1;
        __half2 pl; pl.x = l0; pl.y = l1;
        oh[s] = *reinterpret_cast<uint32_t*>(&ph);
        ol[s] = *reinterpret_cast<uint32_t*>(&pl);
    }
    uint4* dh = reinterpret_cast<uint4*>(g_Xh + base);
    uint4* dl = reinterpret_cast<uint4*>(g_Xl + base);
    dh[0] = make_uint4(oh[0], oh[1], oh[2], oh[3]);
    dh[1] = make_uint4(oh[4], oh[5], oh[6], oh[7]);
    dl[0] = make_uint4(ol[0], ol[1], ol[2], ol[3]);
    dl[1] = make_uint4(ol[4], ol[5], ol[6], ol[7]);
}

// ---------------------------------------------------------------------------
// Kernel 2b: W[e][k][n] -> fp16 W'[e][n][k-perm].
// ---------------------------------------------------------------------------
__global__ void wprep_kernel(const float* __restrict__ W)
{
    __shared__ float tile[32][33];
    int e = blockIdx.z;
    int nb = blockIdx.x * 32, kb = blockIdx.y * 32;
    int tx = threadIdx.x, ty = threadIdx.y;   // 32 x 8
    const float* Ws = W + (size_t)e * D_DIM * D_DIM;
#pragma unroll
    for (int j = 0; j < 32; j += 8)
        tile[ty + j][tx] = Ws[(size_t)(kb + ty + j) * D_DIM + nb + tx];
    __syncthreads();
    int grp = tx >> 4, p = (tx & 15) >> 1, lo = tx & 1;
    int s = (p < 4) ? 2 * p : 2 * (p - 4) + 1;
    int kp = kb + grp * 16 + s * 2 + lo;
#pragma unroll
    for (int j = 0; j < 32; j += 8)
        g_Wh[((size_t)e * D_DIM + nb + ty + j) * D_DIM + kp] =
            __float2half(tile[tx][ty + j]);
}

// ---------------------------------------------------------------------------
// Kernel 3: main GEMM. Grid (8 N-tiles, 256 M-tiles), 256 thr, 2 CTAs/SM.
// CTA tile 128x64; 8 warps (4m x 2n); warp tile 32x32.
// Stage = k16 chunk: X(hi+lo) + B for ALL 8 experts. 32 stages, 3-ring.
// A fragments loaded once per stage, reused by all 8 experts.
// ---------------------------------------------------------------------------
#define XBUF 2048                             // u32: hi 1024 + lo 1024
#define BBUF 4096                             // u32: 8 experts x 64 rows x 8
#define SW_OFF 0                              // [e][m] fp32: 1024 u32
#define BIAS_OFF 1024                         // [e][n] fp32: 512 u32
#define X_OFF 1536                            // 3 buffers
#define B_OFF (X_OFF + 3 * XBUF)              // 7680; 3 buffers
#define SMEM_U32 (B_OFF + 3 * BBUF)           // 19968
#define SMEM_BYTES (SMEM_U32 * 4)             // 79872

__device__ __forceinline__ void issue_stage(
    int tid, uint32_t sm_base, int s, int t0, int n0)
{
    const int buf = s % 3;
    // X hi+lo: 128 rows x 2 chunks each (512 cp16, 2/thread)
    {
        int row = tid >> 1, ch = tid & 1;
        uint32_t dst = sm_base + (X_OFF + buf * XBUF + row * 8 + ch * 4) * 4;
        const size_t src = (size_t)(t0 + row) * D_DIM + s * 16 + ch * 8;
        cp16(dst, g_Xh + src);
        cp16(dst + 1024 * 4, g_Xl + src);
    }
    // B: 8 experts x 64 rows x 2 chunks (1024 cp16, 4/thread)
#pragma unroll
    for (int i = 0; i < 4; i++) {
        int id = tid + (i << 8);
        int e = id >> 7, row = (id >> 1) & 63, ch = id & 1;
        uint32_t dst = sm_base + (B_OFF + buf * BBUF + e * 512 + row * 8 + ch * 4) * 4;
        cp16(dst, g_Wh + ((size_t)e * D_DIM + n0 + row) * D_DIM + s * 16 + ch * 8);
    }
    asm volatile("cp.async.commit_group;\n" ::: "memory");
}

__global__ __launch_bounds__(256, 2) void moe_mma_kernel(
    const float* __restrict__ bexp,
    float* __restrict__ out)
{
    extern __shared__ float smem[];
    uint32_t* smemU = reinterpret_cast<uint32_t*>(smem);
    const uint32_t sm_base = smem_u32(smem);
    const int tid = threadIdx.x;
    const int lane = tid & 31, wid = tid >> 5;
    const int g = lane >> 2, t4 = lane & 3;
    const int wm = (wid >> 1) * 32, wn = (wid & 1) * 32;
    const int n0 = blockIdx.x * 64;
    const int t0 = blockIdx.y * 128;

    // stage gate weights [e][m] and bias [e][n]
    for (int i = tid; i < 128 * E_DIM; i += 256) {
        int m = i >> 3, e = i & 7;
        smem[SW_OFF + e * 128 + m] = g_w[(size_t)(t0 + m) * E_DIM + e];
    }
    for (int i = tid; i < E_DIM * 64; i += 256) {
        int e = i >> 6, c = i & 63;
        smem[BIAS_OFF + i] = bexp[e * D_DIM + n0 + c];
    }

    float o[2][4][4];
#pragma unroll
    for (int mt = 0; mt < 2; mt++)
#pragma unroll
        for (int nt = 0; nt < 4; nt++)
#pragma unroll
            for (int j = 0; j < 4; j++) o[mt][nt][j] = 0.f;

    issue_stage(tid, sm_base, 0, t0, n0);
    issue_stage(tid, sm_base, 1, t0, n0);

#pragma unroll 1
    for (int s = 0; s < 32; ++s) {
        asm volatile("cp.async.wait_group 1;\n" ::: "memory");
        __syncthreads();
        if (s + 2 < 32) issue_stage(tid, sm_base, s + 2, t0, n0);
        else asm volatile("cp.async.commit_group;\n" ::: "memory");

        const int buf = s % 3;
        const uint32_t* Xb = smemU + X_OFF + buf * XBUF;
        const uint32_t* Bb = smemU + B_OFF + buf * BBUF;

        // ---- load A fragments once (hi+lo, both m16 tiles): 8 LDS.64 ----
        uint32_t Ah[2][4], Al[2][4];
#pragma unroll
        for (int mt = 0; mt < 2; mt++) {
            int r = wm + mt * 16 + g;
            uint2 h0 = *reinterpret_cast<const uint2*>(Xb + r * 8 + t4 * 2);
            uint2 h1 = *reinterpret_cast<const uint2*>(Xb + (r + 8) * 8 + t4 * 2);
            uint2 l0 = *reinterpret_cast<const uint2*>(Xb + 1024 + r * 8 + t4 * 2);
            uint2 l1 = *reinterpret_cast<const uint2*>(Xb + 1024 + (r + 8) * 8 + t4 * 2);
            Ah[mt][0] = h0.x; Ah[mt][1] = h1.x; Ah[mt][2] = h0.y; Ah[mt][3] = h1.y;
            Al[mt][0] = l0.x; Al[mt][1] = l1.x; Al[mt][2] = l0.y; Al[mt][3] = l1.y;
        }

        // ---- 8 experts: 4 B LDS.64 + 16 MMAs + fold each ----
#pragma unroll
        for (int e = 0; e < E_DIM; e++) {
            float acc[2][4][4];
#pragma unroll
            for (int mt = 0; mt < 2; mt++)
#pragma unroll
                for (int nt = 0; nt < 4; nt++)
#pragma unroll
                    for (int j = 0; j < 4; j++) acc[mt][nt][j] = 0.f;

#pragma unroll
            for (int nt = 0; nt < 4; nt++) {
                uint2 b = *reinterpret_cast<const uint2*>(
                    Bb + e * 512 + (wn + nt * 8 + g) * 8 + t4 * 2);
                mma_f16(acc[0][nt], Ah[0][0], Ah[0][1], Ah[0][2], Ah[0][3], b.x, b.y);
                mma_f16(acc[1][nt], Ah[1][0], Ah[1][1], Ah[1][2], Ah[1][3], b.x, b.y);
                mma_f16(acc[0][nt], Al[0][0], Al[0][1], Al[0][2], Al[0][3], b.x, b.y);
                mma_f16(acc[1][nt], Al[1][0], Al[1][1], Al[1][2], Al[1][3], b.x, b.y);
            }

#pragma unroll
            for (int mt = 0; mt < 2; mt++) {
                float wv0 = smem[SW_OFF + e * 128 + wm + mt * 16 + g];
                float wv1 = smem[SW_OFF + e * 128 + wm + mt * 16 + g + 8];
#pragma unroll
                for (int nt = 0; nt < 4; nt++) {
                    o[mt][nt][0] = fmaf(wv0, acc[mt][nt][0], o[mt][nt][0]);
                    o[mt][nt][1] = fmaf(wv0, acc[mt][nt][1], o[mt][nt][1]);
                    o[mt][nt][2] = fmaf(wv1, acc[mt][nt][2], o[mt][nt][2]);
                    o[mt][nt][3] = fmaf(wv1, acc[mt][nt][3], o[mt][nt][3]);
                }
            }
        }
    }

    __syncthreads();

    // ---- epilogue: add sum_e w_te * b_e[n], write out ----
#pragma unroll
    for (int mt = 0; mt < 2; mt++) {
#pragma unroll
        for (int rr = 0; rr < 2; rr++) {
            int row = wm + mt * 16 + g + rr * 8;
            float wv[E_DIM];
#pragma unroll
            for (int e = 0; e < E_DIM; e++) wv[e] = smem[SW_OFF + e * 128 + row];
#pragma unroll
            for (int nt = 0; nt < 4; nt++) {
                int cl = wn + nt * 8 + 2 * t4;
                float b0 = 0.f, b1 = 0.f;
#pragma unroll
                for (int e = 0; e < E_DIM; e++) {
                    b0 = fmaf(wv[e], smem[BIAS_OFF + e * 64 + cl], b0);
                    b1 = fmaf(wv[e], smem[BIAS_OFF + e * 64 + cl + 1], b1);
                }
                float2 v;
                v.x = o[mt][nt][rr * 2 + 0] + b0;
                v.y = o[mt][nt][rr * 2 + 1] + b1;
                *reinterpret_cast<float2*>(out + (size_t)(t0 + row) * D_DIM + n0 + cl) = v;
            }
        }
    }
}

// ---------------------------------------------------------------------------
extern "C" void kernel_launch(void* const* d_in, const int* in_sizes, int n_in,
                              void* d_out, int out_size)
{
    const float* x    = (const float*)d_in[0];
    const float* Wg   = (const float*)d_in[1];
    const float* bg   = (const float*)d_in[2];
    const float* Wt   = (const float*)d_in[3];
    const float* bt   = (const float*)d_in[4];
    const float* Wexp = (const float*)d_in[5];
    const float* bexp = (const float*)d_in[6];
    float* out        = (float*)d_out;

    const int T = in_sizes[0] / D_DIM;          // 32768

    cudaFuncSetAttribute(moe_mma_kernel,
                         cudaFuncAttributeMaxDynamicSharedMemorySize, SMEM_BYTES);

    gating_kernel<<<T / 8, 256>>>(x, Wg, bg, Wt, bt);
    xprep_kernel<<<T * D_DIM / 16 / 256, 256>>>(x);
    wprep_kernel<<<dim3(16, 16, 8), dim3(32, 8)>>>(Wexp);
    moe_mma_kernel<<<dim3(8, T / 128), 256, SMEM_BYTES>>>(bexp, out);
}

// round 10
// speedup vs baseline: 1.2091x; 1.2091x over previous
#include <cuda_runtime.h>
#include <cuda_fp16.h>
#include <cstdint>

// AdaMoeLayer: out[t] = sum_e w[t,e]*(x[t] @ W_e + b_e),  T=32768, D=512, E=8.
// fp16 mma.sync m16n8k16, X split hi/lo, W fp16. R10: stage = (k64, expert);
// A fragments held in regs across the 8 experts of each k64 chunk; fold+zero
// amortized over 64 MMAs; XOR-swizzled pad-free SMEM (104KB, 2 CTAs/SM).

#define D_DIM 512
#define E_DIM 8
#define T_TOK 32768
#define MAX_THRESHOLD 0.25f

// ---- static device scratch ----
__device__ float g_w[T_TOK * E_DIM];                       // gate weights, 1 MB
__device__ __half g_Wh[(size_t)E_DIM * D_DIM * D_DIM];     // fp16 W' [e][n][k-perm], 4 MB
__device__ __half g_Xh[(size_t)T_TOK * D_DIM];             // fp16 X hi [t][k-perm], 32 MB
__device__ __half g_Xl[(size_t)T_TOK * D_DIM];             // fp16 X lo [t][k-perm], 32 MB

// ---------------------------------------------------------------------------
__device__ __forceinline__ uint32_t smem_u32(const void* p) {
    uint32_t a;
    asm("{ .reg .u64 t; cvta.to.shared.u64 t, %1; cvt.u32.u64 %0, t; }"
        : "=r"(a) : "l"(p));
    return a;
}
__device__ __forceinline__ void cp16(uint32_t dst, const void* src) {
    asm volatile("cp.async.cg.shared.global [%0], [%1], 16;\n"
                 :: "r"(dst), "l"(__cvta_generic_to_global(src)) : "memory");
}
__device__ __forceinline__ void mma_f16(float* c,
    uint32_t a0, uint32_t a1, uint32_t a2, uint32_t a3,
    uint32_t b0, uint32_t b1)
{
    asm volatile(
        "mma.sync.aligned.m16n8k16.row.col.f32.f16.f16.f32 "
        "{%0,%1,%2,%3}, {%4,%5,%6,%7}, {%8,%9}, {%0,%1,%2,%3};"
        : "+f"(c[0]), "+f"(c[1]), "+f"(c[2]), "+f"(c[3])
        : "r"(a0), "r"(a1), "r"(a2), "r"(a3), "r"(b0), "r"(b1));
}

// ---------------------------------------------------------------------------
// Kernel 1: gating. One warp per token.
// ---------------------------------------------------------------------------
__global__ __launch_bounds__(256) void gating_kernel(
    const float* __restrict__ x,
    const float* __restrict__ Wg, const float* __restrict__ bg,
    const float* __restrict__ Wt, const float* __restrict__ bt)
{
    __shared__ float sWg[E_DIM][D_DIM];
    __shared__ float sWt[D_DIM];
    const int tid = threadIdx.x;
    for (int i = tid; i < E_DIM * D_DIM; i += 256) {
        int e = i / D_DIM, d = i - e * D_DIM;
        sWg[e][d] = Wg[d * E_DIM + e];
    }
    for (int i = tid; i < D_DIM; i += 256) sWt[i] = Wt[i];
    __syncthreads();

    const int warp = tid >> 5, lane = tid & 31;
    const int t = blockIdx.x * 8 + warp;
    const float* xr = x + (size_t)t * D_DIM;

    float acc[9];
#pragma unroll
    for (int e = 0; e < 9; e++) acc[e] = 0.f;
#pragma unroll
    for (int i = 0; i < D_DIM / 32; i++) {
        int d = lane + 32 * i;
        float xv = xr[d];
#pragma unroll
        for (int e = 0; e < E_DIM; e++) acc[e] = fmaf(xv, sWg[e][d], acc[e]);
        acc[8] = fmaf(xv, sWt[d], acc[8]);
    }
#pragma unroll
    for (int off = 16; off > 0; off >>= 1)
#pragma unroll
        for (int e = 0; e < 9; e++) acc[e] += __shfl_xor_sync(0xffffffffu, acc[e], off);

    float logit[E_DIM];
#pragma unroll
    for (int e = 0; e < E_DIM; e++) logit[e] = acc[e] + bg[e];
    float m = logit[0];
#pragma unroll
    for (int e = 1; e < E_DIM; e++) m = fmaxf(m, logit[e]);
    float p[E_DIM], s = 0.f;
#pragma unroll
    for (int e = 0; e < E_DIM; e++) { p[e] = expf(logit[e] - m); s += p[e]; }
    float inv_s = 1.f / s;
    float thr = (1.f / (1.f + expf(-(acc[8] + bt[0])))) * MAX_THRESHOLD;

    float w[E_DIM], ws = 0.f;
#pragma unroll
    for (int e = 0; e < E_DIM; e++) {
        float a = p[e] * inv_s - thr;
        w[e] = (a >= 0.f) ? a : 0.f;
        ws += w[e];
    }
    if (ws == 0.f) ws = 1.f;
    float inv_ws = 1.f / ws;

    if (lane < E_DIM) {
        float v = 0.f;
#pragma unroll
        for (int e = 0; e < E_DIM; e++) if (lane == e) v = w[e];
        g_w[t * E_DIM + lane] = v * inv_ws;
    }
}

// ---------------------------------------------------------------------------
// Kernel 2a: X -> fp16 hi/lo, pair-permuted within each 16-k group.
// Pair p (0..7) stored at u32 slot s(p) = p<4 ? 2p : 2(p-4)+1.
// ---------------------------------------------------------------------------
__global__ __launch_bounds__(256) void xprep_kernel(const float* __restrict__ X)
{
    size_t idx = (size_t)blockIdx.x * 256 + threadIdx.x;
    size_t base = idx * 16;
    float v[16];
#pragma unroll
    for (int i = 0; i < 4; i++)
        *reinterpret_cast<float4*>(v + i * 4) =
            *reinterpret_cast<const float4*>(X + base + i * 4);

    uint32_t oh[8], ol[8];
#pragma unroll
    for (int p = 0; p < 8; p++) {
        float v0 = v[2 * p], v1 = v[2 * p + 1];
        __half h0 = __float2half(v0), h1 = __float2half(v1);
        __half l0 = __float2half(v0 - __half2float(h0));
        __half l1 = __float2half(v1 - __half2float(h1));
        int s = (p < 4) ? 2 * p : 2 * (p - 4) + 1;
        __half2 ph; ph.x = h0; ph.y = h1;
        __half2 pl; pl.x = l0; pl.y = l1;
        oh[s] = *reinterpret_cast<uint32_t*>(&ph);
        ol[s] = *reinterpret_cast<uint32_t*>(&pl);
    }
    uint4* dh = reinterpret_cast<uint4*>(g_Xh + base);
    uint4* dl = reinterpret_cast<uint4*>(g_Xl + base);
    dh[0] = make_uint4(oh[0], oh[1], oh[2], oh[3]);
    dh[1] = make_uint4(oh[4], oh[5], oh[6], oh[7]);
    dl[0] = make_uint4(ol[0], ol[1], ol[2], ol[3]);
    dl[1] = make_uint4(ol[4], ol[5], ol[6], ol[7]);
}

// ---------------------------------------------------------------------------
// Kernel 2b: W[e][k][n] -> fp16 W'[e][n][k-perm].
// ---------------------------------------------------------------------------
__global__ void wprep_kernel(const float* __restrict__ W)
{
    __shared__ float tile[32][33];
    int e = blockIdx.z;
    int nb = blockIdx.x * 32, kb = blockIdx.y * 32;
    int tx = threadIdx.x, ty = threadIdx.y;   // 32 x 8
    const float* Ws = W + (size_t)e * D_DIM * D_DIM;
#pragma unroll
    for (int j = 0; j < 32; j += 8)
        tile[ty + j][tx] = Ws[(size_t)(kb + ty + j) * D_DIM + nb + tx];
    __syncthreads();
    int grp = tx >> 4, p = (tx & 15) >> 1, lo = tx & 1;
    int s = (p < 4) ? 2 * p : 2 * (p - 4) + 1;
    int kp = kb + grp * 16 + s * 2 + lo;
#pragma unroll
    for (int j = 0; j < 32; j += 8)
        g_Wh[((size_t)e * D_DIM + nb + ty + j) * D_DIM + kp] =
            __float2half(tile[tx][ty + j]);
}

// ---------------------------------------------------------------------------
// Kernel 3: main GEMM. Grid (8 N-tiles, 256 M-tiles), 256 thr, 2 CTAs/SM.
// CTA tile 128x64; 8 warps, each a 16x64 strip (1 m16 x 8 n8).
// Stage = (k64 chunk, expert): 8 kt x 8 e = 64 stages. A frags (32 regs)
// loaded once per kt; B 4-ring; X double buffer. XOR-swizzled SMEM, no pads.
// Per expert: 32 B-LDS.64 + 64 MMA + 32 fold FMA.
// ---------------------------------------------------------------------------
#define XCOMP 4096                            // u32 per hi/lo comp (128 rows x 32)
#define XBUF (2 * XCOMP)                      // 8192
#define BBUF 2048                             // 64 rows x 32 u32
#define SW_OFF 0                              // [e][m] fp32: 1024 u32
#define BIAS_OFF 1024                         // [e][n] fp32: 512 u32
#define X_OFF 1536                            // 2 buffers
#define B_OFF (X_OFF + 2 * XBUF)              // 17920; 4 buffers
#define SMEM_U32 (B_OFF + 4 * BBUF)           // 26112
#define SMEM_BYTES (SMEM_U32 * 4)             // 104448

// word offset within a row: chunk ch (16B) at ((ch*4) ^ ((row&3)*8))
__device__ __forceinline__ void issue_X(int tid, uint32_t sm_base, int kt, int t0)
{
    const int buf = kt & 1;
#pragma unroll
    for (int i = 0; i < 4; i++) {
        int id = tid + (i << 8);
        int row = id >> 3, ch = id & 7;
        uint32_t wo = (uint32_t)((ch * 4) ^ ((row & 3) * 8));
        uint32_t dst = sm_base + (X_OFF + buf * XBUF + row * 32 + wo) * 4;
        const size_t src = (size_t)(t0 + row) * D_DIM + kt * 64 + ch * 8;
        cp16(dst, g_Xh + src);
        cp16(dst + XCOMP * 4, g_Xl + src);
    }
}
__device__ __forceinline__ void issue_B(
    int tid, uint32_t sm_base, int e, int kt, int buf, int n0)
{
#pragma unroll
    for (int i = 0; i < 2; i++) {
        int id = tid + (i << 8);
        int row = id >> 3, ch = id & 7;
        uint32_t wo = (uint32_t)((ch * 4) ^ ((row & 3) * 8));
        uint32_t dst = sm_base + (B_OFF + buf * BBUF + row * 32 + wo) * 4;
        cp16(dst, g_Wh + ((size_t)e * D_DIM + n0 + row) * D_DIM + kt * 64 + ch * 8);
    }
}

__global__ __launch_bounds__(256, 2) void moe_mma_kernel(
    const float* __restrict__ bexp,
    float* __restrict__ out)
{
    extern __shared__ float smem[];
    uint32_t* smemU = reinterpret_cast<uint32_t*>(smem);
    const uint32_t sm_base = smem_u32(smem);
    const int tid = threadIdx.x;
    const int lane = tid & 31, wid = tid >> 5;
    const int g = lane >> 2, t4 = lane & 3;
    const int n0 = blockIdx.x * 64;
    const int t0 = blockIdx.y * 128;
    const int r0 = wid * 16 + g;
    const int swz = (g & 3) * 8;               // XOR swizzle term for reads

    // stage gate weights [e][m] and bias [e][n]
    for (int i = tid; i < 128 * E_DIM; i += 256) {
        int m = i >> 3, e = i & 7;
        smem[SW_OFF + e * 128 + m] = g_w[(size_t)(t0 + m) * E_DIM + e];
    }
    for (int i = tid; i < E_DIM * 64; i += 256) {
        int e = i >> 6, c = i & 63;
        smem[BIAS_OFF + i] = bexp[e * D_DIM + n0 + c];
    }

    float o[8][4];
#pragma unroll
    for (int nt = 0; nt < 8; nt++)
#pragma unroll
        for (int j = 0; j < 4; j++) o[nt][j] = 0.f;

    // prologue
    issue_X(tid, sm_base, 0, t0);
    issue_B(tid, sm_base, 0, 0, 0, n0);
    asm volatile("cp.async.commit_group;\n" ::: "memory");
    issue_B(tid, sm_base, 1, 0, 1, n0);
    asm volatile("cp.async.commit_group;\n" ::: "memory");

#pragma unroll 1
    for (int kt = 0; kt < 8; ++kt) {
        const uint32_t* Xb = smemU + X_OFF + (kt & 1) * XBUF;
        uint32_t Ah[4][4], Al[4][4];
#pragma unroll
        for (int e = 0; e < E_DIM; e++) {
            const int s = kt * 8 + e;
            if (s < 63) asm volatile("cp.async.wait_group 1;\n" ::: "memory");
            else        asm volatile("cp.async.wait_group 0;\n" ::: "memory");
            __syncthreads();

            // prefetch stage s+2
            if (s + 2 < 64) {
                const int e2 = (e + 2) & 7;
                const int kt2 = kt + (e >= 6 ? 1 : 0);
                if (e2 == 0) issue_X(tid, sm_base, kt2, t0);
                issue_B(tid, sm_base, e2, kt2, (e + 2) & 3, n0);
            }
            asm volatile("cp.async.commit_group;\n" ::: "memory");

            // load A fragments once per kt (after X(kt) is certainly resident)
            if (e == 0) {
#pragma unroll
                for (int j = 0; j < 4; j++) {
                    uint32_t wo = (uint32_t)((j * 8 + t4 * 2) ^ swz);
                    uint2 h0 = *reinterpret_cast<const uint2*>(Xb + r0 * 32 + wo);
                    uint2 h1 = *reinterpret_cast<const uint2*>(Xb + (r0 + 8) * 32 + wo);
                    uint2 l0 = *reinterpret_cast<const uint2*>(Xb + XCOMP + r0 * 32 + wo);
                    uint2 l1 = *reinterpret_cast<const uint2*>(Xb + XCOMP + (r0 + 8) * 32 + wo);
                    Ah[j][0] = h0.x; Ah[j][1] = h1.x; Ah[j][2] = h0.y; Ah[j][3] = h1.y;
                    Al[j][0] = l0.x; Al[j][1] = l1.x; Al[j][2] = l0.y; Al[j][3] = l1.y;
                }
            }

            const uint32_t* Bb = smemU + B_OFF + (e & 3) * BBUF;

            float acc[8][4];
#pragma unroll
            for (int nt = 0; nt < 8; nt++)
#pragma unroll
                for (int j = 0; j < 4; j++) acc[nt][j] = 0.f;

#pragma unroll
            for (int j = 0; j < 4; j++) {
                uint32_t wo = (uint32_t)((j * 8 + t4 * 2) ^ swz);
#pragma unroll
                for (int nt = 0; nt < 8; nt++) {
                    uint2 b = *reinterpret_cast<const uint2*>(
                        Bb + (nt * 8 + g) * 32 + wo);
                    mma_f16(acc[nt], Ah[j][0], Ah[j][1], Ah[j][2], Ah[j][3], b.x, b.y);
                    mma_f16(acc[nt], Al[j][0], Al[j][1], Al[j][2], Al[j][3], b.x, b.y);
                }
            }

            // fold this expert's partial into o
            {
                float wv0 = smem[SW_OFF + e * 128 + r0];
                float wv1 = smem[SW_OFF + e * 128 + r0 + 8];
#pragma unroll
                for (int nt = 0; nt < 8; nt++) {
                    o[nt][0] = fmaf(wv0, acc[nt][0], o[nt][0]);
                    o[nt][1] = fmaf(wv0, acc[nt][1], o[nt][1]);
                    o[nt][2] = fmaf(wv1, acc[nt][2], o[nt][2]);
                    o[nt][3] = fmaf(wv1, acc[nt][3], o[nt][3]);
                }
            }
        }
    }

    __syncthreads();

    // ---- epilogue: add sum_e w_te * b_e[n], write out ----
#pragma unroll
    for (int rr = 0; rr < 2; rr++) {
        int row = r0 + rr * 8;
        float wv[E_DIM];
#pragma unroll
        for (int e = 0; e < E_DIM; e++) wv[e] = smem[SW_OFF + e * 128 + row];
#pragma unroll
        for (int nt = 0; nt < 8; nt++) {
            int cl = nt * 8 + 2 * t4;
            float b0 = 0.f, b1 = 0.f;
#pragma unroll
            for (int e = 0; e < E_DIM; e++) {
                b0 = fmaf(wv[e], smem[BIAS_OFF + e * 64 + cl], b0);
                b1 = fmaf(wv[e], smem[BIAS_OFF + e * 64 + cl + 1], b1);
            }
            float2 v;
            v.x = o[nt][rr * 2 + 0] + b0;
            v.y = o[nt][rr * 2 + 1] + b1;
            *reinterpret_cast<float2*>(out + (size_t)(t0 + row) * D_DIM + n0 + cl) = v;
        }
    }
}

// ---------------------------------------------------------------------------
extern "C" void kernel_launch(void* const* d_in, const int* in_sizes, int n_in,
                              void* d_out, int out_size)
{
    const float* x    = (const float*)d_in[0];
    const float* Wg   = (const float*)d_in[1];
    const float* bg   = (const float*)d_in[2];
    const float* Wt   = (const float*)d_in[3];
    const float* bt   = (const float*)d_in[4];
    const float* Wexp = (const float*)d_in[5];
    const float* bexp = (const float*)d_in[6];
    float* out        = (float*)d_out;

    const int T = in_sizes[0] / D_DIM;          // 32768

    cudaFuncSetAttribute(moe_mma_kernel,
                         cudaFuncAttributeMaxDynamicSharedMemorySize, SMEM_BYTES);

    gating_kernel<<<T / 8, 256>>>(x, Wg, bg, Wt, bt);
    xprep_kernel<<<T * D_DIM / 16 / 256, 256>>>(x);
    wprep_kernel<<<dim3(16, 16, 8), dim3(32, 8)>>>(Wexp);
    moe_mma_kernel<<<dim3(8, T / 128), 256, SMEM_BYTES>>>(bexp, out);
}

// round 11
// speedup vs baseline: 2.3141x; 1.9139x over previous
#include <cuda_runtime.h>
#include <cuda_fp16.h>
#include <cstdint>

// AdaMoeLayer: out[t] = sum_e w[t,e]*(x[t] @ W_e + b_e),  T=32768, D=512, E=8.
// R11: SPARSE grouped GEMM. Gating builds per-expert token lists (w>0 only);
// per-expert gathered fp16 hi/lo mma GEMM; epilogue atomicAdd w*acc into out;
// bias term out=sum_e w_e*b_e written by an init kernel. Work scales with
// gate density (predicted ~0.3-0.5 of dense).

#define D_DIM 512
#define E_DIM 8
#define T_TOK 32768
#define MAX_THRESHOLD 0.25f

// ---- static device scratch ----
__device__ float g_w[T_TOK * E_DIM];                       // gate weights, 1 MB
__device__ int   g_cnt[E_DIM];                             // per-expert counts
__device__ int   g_list[(size_t)E_DIM * T_TOK];            // token ids, 1 MB
__device__ float g_wval[(size_t)E_DIM * T_TOK];            // weights,   1 MB
__device__ __half g_Wh[(size_t)E_DIM * D_DIM * D_DIM];     // fp16 W' [e][n][k-perm]
__device__ __half g_Xh[(size_t)T_TOK * D_DIM];             // fp16 X hi [t][k-perm]
__device__ __half g_Xl[(size_t)T_TOK * D_DIM];             // fp16 X lo [t][k-perm]

// ---------------------------------------------------------------------------
__device__ __forceinline__ uint32_t smem_u32(const void* p) {
    uint32_t a;
    asm("{ .reg .u64 t; cvta.to.shared.u64 t, %1; cvt.u32.u64 %0, t; }"
        : "=r"(a) : "l"(p));
    return a;
}
__device__ __forceinline__ void cp16(uint32_t dst, const void* src) {
    asm volatile("cp.async.cg.shared.global [%0], [%1], 16;\n"
                 :: "r"(dst), "l"(__cvta_generic_to_global(src)) : "memory");
}
__device__ __forceinline__ void mma_f16(float* c,
    uint32_t a0, uint32_t a1, uint32_t a2, uint32_t a3,
    uint32_t b0, uint32_t b1)
{
    asm volatile(
        "mma.sync.aligned.m16n8k16.row.col.f32.f16.f16.f32 "
        "{%0,%1,%2,%3}, {%4,%5,%6,%7}, {%8,%9}, {%0,%1,%2,%3};"
        : "+f"(c[0]), "+f"(c[1]), "+f"(c[2]), "+f"(c[3])
        : "r"(a0), "r"(a1), "r"(a2), "r"(a3), "r"(b0), "r"(b1));
}

// ---------------------------------------------------------------------------
// Kernel 0: zero the append state (counts + weight pads).
// ---------------------------------------------------------------------------
__global__ __launch_bounds__(256) void zero_kernel()
{
    int idx = blockIdx.x * 256 + threadIdx.x;              // 256 blocks
    reinterpret_cast<float4*>(g_wval)[idx] = make_float4(0.f, 0.f, 0.f, 0.f);
    if (blockIdx.x == 0 && threadIdx.x < E_DIM) g_cnt[threadIdx.x] = 0;
}

// ---------------------------------------------------------------------------
// Kernel 1: gating + per-expert list append. One warp per token.
// ---------------------------------------------------------------------------
__global__ __launch_bounds__(256) void gating_kernel(
    const float* __restrict__ x,
    const float* __restrict__ Wg, const float* __restrict__ bg,
    const float* __restrict__ Wt, const float* __restrict__ bt)
{
    __shared__ float sWg[E_DIM][D_DIM];
    __shared__ float sWt[D_DIM];
    const int tid = threadIdx.x;
    for (int i = tid; i < E_DIM * D_DIM; i += 256) {
        int e = i / D_DIM, d = i - e * D_DIM;
        sWg[e][d] = Wg[d * E_DIM + e];
    }
    for (int i = tid; i < D_DIM; i += 256) sWt[i] = Wt[i];
    __syncthreads();

    const int warp = tid >> 5, lane = tid & 31;
    const int t = blockIdx.x * 8 + warp;
    const float* xr = x + (size_t)t * D_DIM;

    float acc[9];
#pragma unroll
    for (int e = 0; e < 9; e++) acc[e] = 0.f;
#pragma unroll
    for (int i = 0; i < D_DIM / 32; i++) {
        int d = lane + 32 * i;
        float xv = xr[d];
#pragma unroll
        for (int e = 0; e < E_DIM; e++) acc[e] = fmaf(xv, sWg[e][d], acc[e]);
        acc[8] = fmaf(xv, sWt[d], acc[8]);
    }
#pragma unroll
    for (int off = 16; off > 0; off >>= 1)
#pragma unroll
        for (int e = 0; e < 9; e++) acc[e] += __shfl_xor_sync(0xffffffffu, acc[e], off);

    float logit[E_DIM];
#pragma unroll
    for (int e = 0; e < E_DIM; e++) logit[e] = acc[e] + bg[e];
    float m = logit[0];
#pragma unroll
    for (int e = 1; e < E_DIM; e++) m = fmaxf(m, logit[e]);
    float p[E_DIM], s = 0.f;
#pragma unroll
    for (int e = 0; e < E_DIM; e++) { p[e] = expf(logit[e] - m); s += p[e]; }
    float inv_s = 1.f / s;
    float thr = (1.f / (1.f + expf(-(acc[8] + bt[0])))) * MAX_THRESHOLD;

    float w[E_DIM], ws = 0.f;
#pragma unroll
    for (int e = 0; e < E_DIM; e++) {
        float a = p[e] * inv_s - thr;
        w[e] = (a >= 0.f) ? a : 0.f;
        ws += w[e];
    }
    if (ws == 0.f) ws = 1.f;
    float inv_ws = 1.f / ws;

    if (lane < E_DIM) {
        float v = 0.f;
#pragma unroll
        for (int e = 0; e < E_DIM; e++) if (lane == e) v = w[e];
        v *= inv_ws;
        g_w[t * E_DIM + lane] = v;
        if (v > 0.f) {
            int pos = atomicAdd(&g_cnt[lane], 1);
            g_list[(size_t)lane * T_TOK + pos] = t;
            g_wval[(size_t)lane * T_TOK + pos] = v;
        }
    }
}

// ---------------------------------------------------------------------------
// Kernel 2a: X -> fp16 hi/lo, pair-permuted within each 16-k group.
// ---------------------------------------------------------------------------
__global__ __launch_bounds__(256) void xprep_kernel(const float* __restrict__ X)
{
    size_t idx = (size_t)blockIdx.x * 256 + threadIdx.x;
    size_t base = idx * 16;
    float v[16];
#pragma unroll
    for (int i = 0; i < 4; i++)
        *reinterpret_cast<float4*>(v + i * 4) =
            *reinterpret_cast<const float4*>(X + base + i * 4);

    uint32_t oh[8], ol[8];
#pragma unroll
    for (int p = 0; p < 8; p++) {
        float v0 = v[2 * p], v1 = v[2 * p + 1];
        __half h0 = __float2half(v0), h1 = __float2half(v1);
        __half l0 = __float2half(v0 - __half2float(h0));
        __half l1 = __float2half(v1 - __half2float(h1));
        int s = (p < 4) ? 2 * p : 2 * (p - 4) + 1;
        __half2 ph; ph.x = h0; ph.y = h1;
        __half2 pl; pl.x = l0; pl.y = l1;
        oh[s] = *reinterpret_cast<uint32_t*>(&ph);
        ol[s] = *reinterpret_cast<uint32_t*>(&pl);
    }
    uint4* dh = reinterpret_cast<uint4*>(g_Xh + base);
    uint4* dl = reinterpret_cast<uint4*>(g_Xl + base);
    dh[0] = make_uint4(oh[0], oh[1], oh[2], oh[3]);
    dh[1] = make_uint4(oh[4], oh[5], oh[6], oh[7]);
    dl[0] = make_uint4(ol[0], ol[1], ol[2], ol[3]);
    dl[1] = make_uint4(ol[4], ol[5], ol[6], ol[7]);
}

// ---------------------------------------------------------------------------
// Kernel 2b: W[e][k][n] -> fp16 W'[e][n][k-perm].
// ---------------------------------------------------------------------------
__global__ void wprep_kernel(const float* __restrict__ W)
{
    __shared__ float tile[32][33];
    int e = blockIdx.z;
    int nb = blockIdx.x * 32, kb = blockIdx.y * 32;
    int tx = threadIdx.x, ty = threadIdx.y;   // 32 x 8
    const float* Ws = W + (size_t)e * D_DIM * D_DIM;
#pragma unroll
    for (int j = 0; j < 32; j += 8)
        tile[ty + j][tx] = Ws[(size_t)(kb + ty + j) * D_DIM + nb + tx];
    __syncthreads();
    int grp = tx >> 4, p = (tx & 15) >> 1, lo = tx & 1;
    int s = (p < 4) ? 2 * p : 2 * (p - 4) + 1;
    int kp = kb + grp * 16 + s * 2 + lo;
#pragma unroll
    for (int j = 0; j < 32; j += 8)
        g_Wh[((size_t)e * D_DIM + nb + ty + j) * D_DIM + kp] =
            __float2half(tile[tx][ty + j]);
}

// ---------------------------------------------------------------------------
// Kernel 3: bias init. out[t][n] = sum_e w[t,e] * b_e[n].
// ---------------------------------------------------------------------------
__global__ __launch_bounds__(256) void bias_init_kernel(
    const float* __restrict__ bexp, float* __restrict__ out)
{
    int idx = blockIdx.x * 256 + threadIdx.x;   // T*128 total
    int t = idx >> 7, c4 = (idx & 127) * 4;
    float w[E_DIM];
#pragma unroll
    for (int e = 0; e < E_DIM; e++) w[e] = g_w[t * E_DIM + e];
    float4 a = make_float4(0.f, 0.f, 0.f, 0.f);
#pragma unroll
    for (int e = 0; e < E_DIM; e++) {
        float4 b = *reinterpret_cast<const float4*>(bexp + e * D_DIM + c4);
        a.x = fmaf(w[e], b.x, a.x);
        a.y = fmaf(w[e], b.y, a.y);
        a.z = fmaf(w[e], b.z, a.z);
        a.w = fmaf(w[e], b.w, a.w);
    }
    *reinterpret_cast<float4*>(out + (size_t)t * D_DIM + c4) = a;
}

// ---------------------------------------------------------------------------
// Kernel 4: sparse grouped GEMM. Grid (8 N-tiles, 256 M-tiles, 8 experts),
// 256 thr, 2 CTAs/SM. CTA: 128 gathered tokens x 64 cols, K=512 (8 k64
// chunks, double-buffered). Warp = 16x64 strip. Epilogue: atomicAdd w*acc.
// ---------------------------------------------------------------------------
#define XCOMP 4096                            // u32 per hi/lo comp
#define XBUF (2 * XCOMP)                      // 8192
#define BBUF 2048                             // 64 rows x 32 u32
#define IDX_OFF 0                             // 128 ints
#define WV_OFF 128                            // 128 floats
#define X_OFF 256                             // 2 buffers
#define B_OFF (X_OFF + 2 * XBUF)              // 16640; 2 buffers
#define SMEM_U32 (B_OFF + 2 * BBUF)           // 20736
#define SMEM_BYTES (SMEM_U32 * 4)             // 82944

__device__ __forceinline__ void issue_stage(
    int tid, uint32_t sm_base, const int* sIdx, int e, int kt, int n0)
{
    const int buf = kt & 1;
    // X hi+lo gathered rows: 128 rows x 8 chunks (1024 cp16 x2, 4/thread x2)
#pragma unroll
    for (int i = 0; i < 4; i++) {
        int id = tid + (i << 8);
        int row = id >> 3, ch = id & 7;
        uint32_t wo = (uint32_t)((ch * 4) ^ ((row & 3) * 8));
        uint32_t dst = sm_base + (X_OFF + buf * XBUF + row * 32 + wo) * 4;
        const size_t src = (size_t)sIdx[row] * D_DIM + kt * 64 + ch * 8;
        cp16(dst, g_Xh + src);
        cp16(dst + XCOMP * 4, g_Xl + src);
    }
    // B: 64 rows x 8 chunks (512 cp16, 2/thread)
#pragma unroll
    for (int i = 0; i < 2; i++) {
        int id = tid + (i << 8);
        int row = id >> 3, ch = id & 7;
        uint32_t wo = (uint32_t)((ch * 4) ^ ((row & 3) * 8));
        uint32_t dst = sm_base + (B_OFF + buf * BBUF + row * 32 + wo) * 4;
        cp16(dst, g_Wh + ((size_t)e * D_DIM + n0 + row) * D_DIM + kt * 64 + ch * 8);
    }
    asm volatile("cp.async.commit_group;\n" ::: "memory");
}

__global__ __launch_bounds__(256, 2) void moe_mma_kernel(float* __restrict__ out)
{
    const int e = blockIdx.z;
    const int m0 = blockIdx.y * 128;
    if (m0 >= g_cnt[e]) return;

    extern __shared__ float smem[];
    uint32_t* smemU = reinterpret_cast<uint32_t*>(smem);
    int* sIdx = reinterpret_cast<int*>(smem + IDX_OFF);
    float* sW = smem + WV_OFF;
    const uint32_t sm_base = smem_u32(smem);
    const int tid = threadIdx.x;
    const int lane = tid & 31, wid = tid >> 5;
    const int g = lane >> 2, t4 = lane & 3;
    const int n0 = blockIdx.x * 64;
    const int r0 = wid * 16 + g;
    const int swz = (g & 3) * 8;

    if (tid < 128) {
        sIdx[tid] = g_list[(size_t)e * T_TOK + m0 + tid];
        sW[tid] = g_wval[(size_t)e * T_TOK + m0 + tid];
    }
    __syncthreads();

    float acc[8][4];
#pragma unroll
    for (int nt = 0; nt < 8; nt++)
#pragma unroll
        for (int j = 0; j < 4; j++) acc[nt][j] = 0.f;

    issue_stage(tid, sm_base, sIdx, e, 0, n0);

#pragma unroll 1
    for (int kt = 0; kt < 8; ++kt) {
        if (kt + 1 < 8) issue_stage(tid, sm_base, sIdx, e, kt + 1, n0);
        if (kt + 1 < 8) asm volatile("cp.async.wait_group 1;\n" ::: "memory");
        else            asm volatile("cp.async.wait_group 0;\n" ::: "memory");
        __syncthreads();

        const uint32_t* Xb = smemU + X_OFF + (kt & 1) * XBUF;
        const uint32_t* Bb = smemU + B_OFF + (kt & 1) * BBUF;

        uint32_t Ah[4][4], Al[4][4];
#pragma unroll
        for (int j = 0; j < 4; j++) {
            uint32_t wo = (uint32_t)((j * 8 + t4 * 2) ^ swz);
            uint2 h0 = *reinterpret_cast<const uint2*>(Xb + r0 * 32 + wo);
            uint2 h1 = *reinterpret_cast<const uint2*>(Xb + (r0 + 8) * 32 + wo);
            uint2 l0 = *reinterpret_cast<const uint2*>(Xb + XCOMP + r0 * 32 + wo);
            uint2 l1 = *reinterpret_cast<const uint2*>(Xb + XCOMP + (r0 + 8) * 32 + wo);
            Ah[j][0] = h0.x; Ah[j][1] = h1.x; Ah[j][2] = h0.y; Ah[j][3] = h1.y;
            Al[j][0] = l0.x; Al[j][1] = l1.x; Al[j][2] = l0.y; Al[j][3] = l1.y;
        }

#pragma unroll
        for (int j = 0; j < 4; j++) {
            uint32_t wo = (uint32_t)((j * 8 + t4 * 2) ^ swz);
#pragma unroll
            for (int nt = 0; nt < 8; nt++) {
                uint2 b = *reinterpret_cast<const uint2*>(Bb + (nt * 8 + g) * 32 + wo);
                mma_f16(acc[nt], Ah[j][0], Ah[j][1], Ah[j][2], Ah[j][3], b.x, b.y);
                mma_f16(acc[nt], Al[j][0], Al[j][1], Al[j][2], Al[j][3], b.x, b.y);
            }
        }
        __syncthreads();   // all reads done before next overwrite of this buf
    }

    // ---- epilogue: out[t][n] += w * acc (atomic; pads have w==0) ----
#pragma unroll
    for (int rr = 0; rr < 2; rr++) {
        int row_l = r0 + rr * 8;
        float wv = sW[row_l];
        if (wv > 0.f) {
            float* base = out + (size_t)sIdx[row_l] * D_DIM + n0;
#pragma unroll
            for (int nt = 0; nt < 8; nt++) {
                int cl = nt * 8 + 2 * t4;
                atomicAdd(base + cl,     wv * acc[nt][rr * 2 + 0]);
                atomicAdd(base + cl + 1, wv * acc[nt][rr * 2 + 1]);
            }
        }
    }
}

// ---------------------------------------------------------------------------
extern "C" void kernel_launch(void* const* d_in, const int* in_sizes, int n_in,
                              void* d_out, int out_size)
{
    const float* x    = (const float*)d_in[0];
    const float* Wg   = (const float*)d_in[1];
    const float* bg   = (const float*)d_in[2];
    const float* Wt   = (const float*)d_in[3];
    const float* bt   = (const float*)d_in[4];
    const float* Wexp = (const float*)d_in[5];
    const float* bexp = (const float*)d_in[6];
    float* out        = (float*)d_out;

    const int T = in_sizes[0] / D_DIM;          // 32768

    cudaFuncSetAttribute(moe_mma_kernel,
                         cudaFuncAttributeMaxDynamicSharedMemorySize, SMEM_BYTES);

    zero_kernel<<<E_DIM * T_TOK / 4 / 256, 256>>>();
    gating_kernel<<<T / 8, 256>>>(x, Wg, bg, Wt, bt);
    xprep_kernel<<<T * D_DIM / 16 / 256, 256>>>(x);
    wprep_kernel<<<dim3(16, 16, 8), dim3(32, 8)>>>(Wexp);
    bias_init_kernel<<<T * 128 / 256, 256>>>(bexp, out);
    moe_mma_kernel<<<dim3(8, T / 128, E_DIM), 256, SMEM_BYTES>>>(out);
}

// round 12
// speedup vs baseline: 2.4050x; 1.0392x over previous
#include <cuda_runtime.h>
#include <cuda_fp16.h>
#include <cstdint>

// AdaMoeLayer: out[t] = sum_e w[t,e]*(x[t] @ W_e + b_e),  T=32768, D=512, E=8.
// R12: sparse grouped GEMM, BN=128 (halved X gather traffic), single-sync
// pipeline, xprep fused into gating. fp16 hi/lo mma, atomic scatter epilogue.

#define D_DIM 512
#define E_DIM 8
#define T_TOK 32768
#define MAX_THRESHOLD 0.25f

// ---- static device scratch ----
__device__ float g_w[T_TOK * E_DIM];                       // gate weights, 1 MB
__device__ int   g_cnt[E_DIM];                             // per-expert counts
__device__ int   g_list[(size_t)E_DIM * T_TOK];            // token ids, 1 MB
__device__ float g_wval[(size_t)E_DIM * T_TOK];            // weights,   1 MB
__device__ __half g_Wh[(size_t)E_DIM * D_DIM * D_DIM];     // fp16 W' [e][n][k-perm]
__device__ __half g_Xh[(size_t)T_TOK * D_DIM];             // fp16 X hi [t][k-perm]
__device__ __half g_Xl[(size_t)T_TOK * D_DIM];             // fp16 X lo [t][k-perm]

// ---------------------------------------------------------------------------
__device__ __forceinline__ uint32_t smem_u32(const void* p) {
    uint32_t a;
    asm("{ .reg .u64 t; cvta.to.shared.u64 t, %1; cvt.u32.u64 %0, t; }"
        : "=r"(a) : "l"(p));
    return a;
}
__device__ __forceinline__ void cp16(uint32_t dst, const void* src) {
    asm volatile("cp.async.cg.shared.global [%0], [%1], 16;\n"
                 :: "r"(dst), "l"(__cvta_generic_to_global(src)) : "memory");
}
__device__ __forceinline__ void mma_f16(float* c,
    uint32_t a0, uint32_t a1, uint32_t a2, uint32_t a3,
    uint32_t b0, uint32_t b1)
{
    asm volatile(
        "mma.sync.aligned.m16n8k16.row.col.f32.f16.f16.f32 "
        "{%0,%1,%2,%3}, {%4,%5,%6,%7}, {%8,%9}, {%0,%1,%2,%3};"
        : "+f"(c[0]), "+f"(c[1]), "+f"(c[2]), "+f"(c[3])
        : "r"(a0), "r"(a1), "r"(a2), "r"(a3), "r"(b0), "r"(b1));
}

// ---------------------------------------------------------------------------
// Kernel 0: zero the append state (counts + weight pads).
// ---------------------------------------------------------------------------
__global__ __launch_bounds__(256) void zero_kernel()
{
    int idx = blockIdx.x * 256 + threadIdx.x;
    reinterpret_cast<float4*>(g_wval)[idx] = make_float4(0.f, 0.f, 0.f, 0.f);
    if (blockIdx.x == 0 && threadIdx.x < E_DIM) g_cnt[threadIdx.x] = 0;
}

// ---------------------------------------------------------------------------
// Kernel 1: gating + list append + fused X->fp16 hi/lo (pair-permuted).
// One warp per token.
// ---------------------------------------------------------------------------
__global__ __launch_bounds__(256) void gating_kernel(
    const float* __restrict__ x,
    const float* __restrict__ Wg, const float* __restrict__ bg,
    const float* __restrict__ Wt, const float* __restrict__ bt)
{
    __shared__ float sWg[E_DIM][D_DIM];
    __shared__ float sWt[D_DIM];
    const int tid = threadIdx.x;
    for (int i = tid; i < E_DIM * D_DIM; i += 256) {
        int e = i / D_DIM, d = i - e * D_DIM;
        sWg[e][d] = Wg[d * E_DIM + e];
    }
    for (int i = tid; i < D_DIM; i += 256) sWt[i] = Wt[i];
    __syncthreads();

    const int warp = tid >> 5, lane = tid & 31;
    const int t = blockIdx.x * 8 + warp;
    const float* xr = x + (size_t)t * D_DIM;
    uint32_t* xh_u = reinterpret_cast<uint32_t*>(g_Xh) + (size_t)t * 256;
    uint32_t* xl_u = reinterpret_cast<uint32_t*>(g_Xl) + (size_t)t * 256;

    float acc[9];
#pragma unroll
    for (int e = 0; e < 9; e++) acc[e] = 0.f;
#pragma unroll
    for (int i = 0; i < 8; i++) {
        int d = 2 * lane + 64 * i;
        float2 xv = *reinterpret_cast<const float2*>(xr + d);
#pragma unroll
        for (int e = 0; e < E_DIM; e++)
            acc[e] = fmaf(xv.y, sWg[e][d + 1], fmaf(xv.x, sWg[e][d], acc[e]));
        acc[8] = fmaf(xv.y, sWt[d + 1], fmaf(xv.x, sWt[d], acc[8]));

        // fused hi/lo fp16 conversion, pair-permuted slot
        __half h0 = __float2half(xv.x), h1 = __float2half(xv.y);
        __half l0 = __float2half(xv.x - __half2float(h0));
        __half l1 = __float2half(xv.y - __half2float(h1));
        int pg = lane + 32 * i;               // global pair index
        int g16 = pg >> 3, p = pg & 7;
        int s = (p < 4) ? 2 * p : 2 * (p - 4) + 1;
        __half2 ph; ph.x = h0; ph.y = h1;
        __half2 pl; pl.x = l0; pl.y = l1;
        xh_u[g16 * 8 + s] = *reinterpret_cast<uint32_t*>(&ph);
        xl_u[g16 * 8 + s] = *reinterpret_cast<uint32_t*>(&pl);
    }
#pragma unroll
    for (int off = 16; off > 0; off >>= 1)
#pragma unroll
        for (int e = 0; e < 9; e++) acc[e] += __shfl_xor_sync(0xffffffffu, acc[e], off);

    float logit[E_DIM];
#pragma unroll
    for (int e = 0; e < E_DIM; e++) logit[e] = acc[e] + bg[e];
    float m = logit[0];
#pragma unroll
    for (int e = 1; e < E_DIM; e++) m = fmaxf(m, logit[e]);
    float p[E_DIM], s = 0.f;
#pragma unroll
    for (int e = 0; e < E_DIM; e++) { p[e] = expf(logit[e] - m); s += p[e]; }
    float inv_s = 1.f / s;
    float thr = (1.f / (1.f + expf(-(acc[8] + bt[0])))) * MAX_THRESHOLD;

    float w[E_DIM], ws = 0.f;
#pragma unroll
    for (int e = 0; e < E_DIM; e++) {
        float a = p[e] * inv_s - thr;
        w[e] = (a >= 0.f) ? a : 0.f;
        ws += w[e];
    }
    if (ws == 0.f) ws = 1.f;
    float inv_ws = 1.f / ws;

    if (lane < E_DIM) {
        float v = 0.f;
#pragma unroll
        for (int e = 0; e < E_DIM; e++) if (lane == e) v = w[e];
        v *= inv_ws;
        g_w[t * E_DIM + lane] = v;
        if (v > 0.f) {
            int pos = atomicAdd(&g_cnt[lane], 1);
            g_list[(size_t)lane * T_TOK + pos] = t;
            g_wval[(size_t)lane * T_TOK + pos] = v;
        }
    }
}

// ---------------------------------------------------------------------------
// Kernel 2: W[e][k][n] -> fp16 W'[e][n][k-perm].
// ---------------------------------------------------------------------------
__global__ void wprep_kernel(const float* __restrict__ W)
{
    __shared__ float tile[32][33];
    int e = blockIdx.z;
    int nb = blockIdx.x * 32, kb = blockIdx.y * 32;
    int tx = threadIdx.x, ty = threadIdx.y;   // 32 x 8
    const float* Ws = W + (size_t)e * D_DIM * D_DIM;
#pragma unroll
    for (int j = 0; j < 32; j += 8)
        tile[ty + j][tx] = Ws[(size_t)(kb + ty + j) * D_DIM + nb + tx];
    __syncthreads();
    int grp = tx >> 4, p = (tx & 15) >> 1, lo = tx & 1;
    int s = (p < 4) ? 2 * p : 2 * (p - 4) + 1;
    int kp = kb + grp * 16 + s * 2 + lo;
#pragma unroll
    for (int j = 0; j < 32; j += 8)
        g_Wh[((size_t)e * D_DIM + nb + ty + j) * D_DIM + kp] =
            __float2half(tile[tx][ty + j]);
}

// ---------------------------------------------------------------------------
// Kernel 3: bias init. out[t][n] = sum_e w[t,e] * b_e[n].
// ---------------------------------------------------------------------------
__global__ __launch_bounds__(256) void bias_init_kernel(
    const float* __restrict__ bexp, float* __restrict__ out)
{
    int idx = blockIdx.x * 256 + threadIdx.x;   // T*128 total
    int t = idx >> 7, c4 = (idx & 127) * 4;
    float w[E_DIM];
#pragma unroll
    for (int e = 0; e < E_DIM; e++) w[e] = g_w[t * E_DIM + e];
    float4 a = make_float4(0.f, 0.f, 0.f, 0.f);
#pragma unroll
    for (int e = 0; e < E_DIM; e++) {
        float4 b = *reinterpret_cast<const float4*>(bexp + e * D_DIM + c4);
        a.x = fmaf(w[e], b.x, a.x);
        a.y = fmaf(w[e], b.y, a.y);
        a.z = fmaf(w[e], b.z, a.z);
        a.w = fmaf(w[e], b.w, a.w);
    }
    *reinterpret_cast<float4*>(out + (size_t)t * D_DIM + c4) = a;
}

// ---------------------------------------------------------------------------
// Kernel 4: sparse grouped GEMM. Grid (4 N-tiles, 256 M-tiles, 8 experts),
// 256 thr, 2 CTAs/SM. CTA: 128 gathered tokens x 128 cols, K=512 (8 k64
// chunks, double-buffered, ONE sync per stage). Warp = 16x128 strip.
// Epilogue: atomicAdd w*acc into out.
// ---------------------------------------------------------------------------
#define XCOMP 4096                            // u32 per hi/lo comp
#define XBUF (2 * XCOMP)                      // 8192
#define BBUF 4096                             // 128 rows x 32 u32
#define IDX_OFF 0                             // 128 ints
#define WV_OFF 128                            // 128 floats
#define X_OFF 256                             // 2 buffers
#define B_OFF (X_OFF + 2 * XBUF)              // 16640; 2 buffers
#define SMEM_U32 (B_OFF + 2 * BBUF)           // 24832
#define SMEM_BYTES (SMEM_U32 * 4)             // 99328

__device__ __forceinline__ void issue_stage(
    int tid, uint32_t sm_base, const int* sIdx, int e, int kt, int n0)
{
    const int buf = kt & 1;
    // X hi+lo gathered rows: 128 rows x 8 chunks each (4/thread x2)
#pragma unroll
    for (int i = 0; i < 4; i++) {
        int id = tid + (i << 8);
        int row = id >> 3, ch = id & 7;
        uint32_t wo = (uint32_t)((ch * 4) ^ ((row & 3) * 8));
        uint32_t dst = sm_base + (X_OFF + buf * XBUF + row * 32 + wo) * 4;
        const size_t src = (size_t)sIdx[row] * D_DIM + kt * 64 + ch * 8;
        cp16(dst, g_Xh + src);
        cp16(dst + XCOMP * 4, g_Xl + src);
    }
    // B: 128 rows x 8 chunks (1024 cp16, 4/thread)
#pragma unroll
    for (int i = 0; i < 4; i++) {
        int id = tid + (i << 8);
        int row = id >> 3, ch = id & 7;
        uint32_t wo = (uint32_t)((ch * 4) ^ ((row & 3) * 8));
        uint32_t dst = sm_base + (B_OFF + buf * BBUF + row * 32 + wo) * 4;
        cp16(dst, g_Wh + ((size_t)e * D_DIM + n0 + row) * D_DIM + kt * 64 + ch * 8);
    }
    asm volatile("cp.async.commit_group;\n" ::: "memory");
}

__global__ __launch_bounds__(256, 2) void moe_mma_kernel(float* __restrict__ out)
{
    const int e = blockIdx.z;
    const int m0 = blockIdx.y * 128;
    if (m0 >= g_cnt[e]) return;

    extern __shared__ float smem[];
    uint32_t* smemU = reinterpret_cast<uint32_t*>(smem);
    int* sIdx = reinterpret_cast<int*>(smem + IDX_OFF);
    float* sW = smem + WV_OFF;
    const uint32_t sm_base = smem_u32(smem);
    const int tid = threadIdx.x;
    const int lane = tid & 31, wid = tid >> 5;
    const int g = lane >> 2, t4 = lane & 3;
    const int n0 = blockIdx.x * 128;
    const int r0 = wid * 16 + g;
    const int swz = (g & 3) * 8;

    if (tid < 128) {
        sIdx[tid] = g_list[(size_t)e * T_TOK + m0 + tid];
        sW[tid] = g_wval[(size_t)e * T_TOK + m0 + tid];
    }
    __syncthreads();

    float acc[16][4];
#pragma unroll
    for (int nt = 0; nt < 16; nt++)
#pragma unroll
        for (int j = 0; j < 4; j++) acc[nt][j] = 0.f;

    issue_stage(tid, sm_base, sIdx, e, 0, n0);

#pragma unroll 1
    for (int kt = 0; kt < 8; ++kt) {
        asm volatile("cp.async.wait_group 0;\n" ::: "memory");
        __syncthreads();                       // stage kt visible; buf^1 free
        if (kt + 1 < 8) issue_stage(tid, sm_base, sIdx, e, kt + 1, n0);

        const uint32_t* Xb = smemU + X_OFF + (kt & 1) * XBUF;
        const uint32_t* Bb = smemU + B_OFF + (kt & 1) * BBUF;

#pragma unroll
        for (int j = 0; j < 4; j++) {
            uint32_t wo = (uint32_t)((j * 8 + t4 * 2) ^ swz);
            uint2 h0 = *reinterpret_cast<const uint2*>(Xb + r0 * 32 + wo);
            uint2 h1 = *reinterpret_cast<const uint2*>(Xb + (r0 + 8) * 32 + wo);
            uint2 l0 = *reinterpret_cast<const uint2*>(Xb + XCOMP + r0 * 32 + wo);
            uint2 l1 = *reinterpret_cast<const uint2*>(Xb + XCOMP + (r0 + 8) * 32 + wo);
#pragma unroll
            for (int nt = 0; nt < 16; nt++) {
                uint2 b = *reinterpret_cast<const uint2*>(Bb + (nt * 8 + g) * 32 + wo);
                mma_f16(acc[nt], h0.x, h1.x, h0.y, h1.y, b.x, b.y);
                mma_f16(acc[nt], l0.x, l1.x, l0.y, l1.y, b.x, b.y);
            }
        }
    }

    // ---- epilogue: out[t][n] += w * acc (atomic; pads have w==0) ----
#pragma unroll
    for (int rr = 0; rr < 2; rr++) {
        int row_l = r0 + rr * 8;
        float wv = sW[row_l];
        if (wv > 0.f) {
            float* base = out + (size_t)sIdx[row_l] * D_DIM + n0;
#pragma unroll
            for (int nt = 0; nt < 16; nt++) {
                int cl = nt * 8 + 2 * t4;
                atomicAdd(base + cl,     wv * acc[nt][rr * 2 + 0]);
                atomicAdd(base + cl + 1, wv * acc[nt][rr * 2 + 1]);
            }
        }
    }
}

// ---------------------------------------------------------------------------
extern "C" void kernel_launch(void* const* d_in, const int* in_sizes, int n_in,
                              void* d_out, int out_size)
{
    const float* x    = (const float*)d_in[0];
    const float* Wg   = (const float*)d_in[1];
    const float* bg   = (const float*)d_in[2];
    const float* Wt   = (const float*)d_in[3];
    const float* bt   = (const float*)d_in[4];
    const float* Wexp = (const float*)d_in[5];
    const float* bexp = (const float*)d_in[6];
    float* out        = (float*)d_out;

    const int T = in_sizes[0] / D_DIM;          // 32768

    cudaFuncSetAttribute(moe_mma_kernel,
                         cudaFuncAttributeMaxDynamicSharedMemorySize, SMEM_BYTES);

    zero_kernel<<<E_DIM * T_TOK / 4 / 256, 256>>>();
    gating_kernel<<<T / 8, 256>>>(x, Wg, bg, Wt, bt);
    wprep_kernel<<<dim3(16, 16, 8), dim3(32, 8)>>>(Wexp);
    bias_init_kernel<<<T * 128 / 256, 256>>>(bexp, out);
    moe_mma_kernel<<<dim3(4, T / 128, E_DIM), 256, SMEM_BYTES>>>(out);
}

// round 13
// speedup vs baseline: 2.4768x; 1.0299x over previous
#include <cuda_runtime.h>
#include <cuda_fp16.h>
#include <cstdint>

// AdaMoeLayer: out[t] = sum_e w[t,e]*(x[t] @ W_e + b_e),  T=32768, D=512, E=8.
// R13: sparse grouped GEMM (BN=128, single-sync pipeline). Bias term fused
// into the gating kernel (out = sum_e w_e*b_e written there); epilogue uses
// red.global.add.v2.f32 (half the scatter issue cost).

#define D_DIM 512
#define E_DIM 8
#define T_TOK 32768
#define MAX_THRESHOLD 0.25f

// ---- static device scratch ----
__device__ float g_w[T_TOK * E_DIM];                       // gate weights, 1 MB
__device__ int   g_cnt[E_DIM];                             // per-expert counts
__device__ int   g_list[(size_t)E_DIM * T_TOK];            // token ids, 1 MB
__device__ float g_wval[(size_t)E_DIM * T_TOK];            // weights,   1 MB
__device__ __half g_Wh[(size_t)E_DIM * D_DIM * D_DIM];     // fp16 W' [e][n][k-perm]
__device__ __half g_Xh[(size_t)T_TOK * D_DIM];             // fp16 X hi [t][k-perm]
__device__ __half g_Xl[(size_t)T_TOK * D_DIM];             // fp16 X lo [t][k-perm]

// ---------------------------------------------------------------------------
__device__ __forceinline__ uint32_t smem_u32(const void* p) {
    uint32_t a;
    asm("{ .reg .u64 t; cvta.to.shared.u64 t, %1; cvt.u32.u64 %0, t; }"
        : "=r"(a) : "l"(p));
    return a;
}
__device__ __forceinline__ void cp16(uint32_t dst, const void* src) {
    asm volatile("cp.async.cg.shared.global [%0], [%1], 16;\n"
                 :: "r"(dst), "l"(__cvta_generic_to_global(src)) : "memory");
}
__device__ __forceinline__ void mma_f16(float* c,
    uint32_t a0, uint32_t a1, uint32_t a2, uint32_t a3,
    uint32_t b0, uint32_t b1)
{
    asm volatile(
        "mma.sync.aligned.m16n8k16.row.col.f32.f16.f16.f32 "
        "{%0,%1,%2,%3}, {%4,%5,%6,%7}, {%8,%9}, {%0,%1,%2,%3};"
        : "+f"(c[0]), "+f"(c[1]), "+f"(c[2]), "+f"(c[3])
        : "r"(a0), "r"(a1), "r"(a2), "r"(a3), "r"(b0), "r"(b1));
}
__device__ __forceinline__ void red_add_v2(float* addr, float v0, float v1) {
    asm volatile("red.global.add.v2.f32 [%0], {%1, %2};"
                 :: "l"(addr), "f"(v0), "f"(v1) : "memory");
}

// ---------------------------------------------------------------------------
// Kernel 0: zero the append state (counts + weight pads).
// ---------------------------------------------------------------------------
__global__ __launch_bounds__(256) void zero_kernel()
{
    int idx = blockIdx.x * 256 + threadIdx.x;
    reinterpret_cast<float4*>(g_wval)[idx] = make_float4(0.f, 0.f, 0.f, 0.f);
    if (blockIdx.x == 0 && threadIdx.x < E_DIM) g_cnt[threadIdx.x] = 0;
}

// ---------------------------------------------------------------------------
// Kernel 1: gating + list append + fused X->fp16 hi/lo + fused bias write:
// out[t][n] = sum_e w[t,e]*b_e[n]. One warp per token.
// ---------------------------------------------------------------------------
__global__ __launch_bounds__(256) void gating_kernel(
    const float* __restrict__ x,
    const float* __restrict__ Wg, const float* __restrict__ bg,
    const float* __restrict__ Wt, const float* __restrict__ bt,
    const float* __restrict__ bexp, float* __restrict__ out)
{
    __shared__ float sWg[E_DIM][D_DIM];
    __shared__ float sWt[D_DIM];
    __shared__ float sB[E_DIM][D_DIM];
    const int tid = threadIdx.x;
    for (int i = tid; i < E_DIM * D_DIM; i += 256) {
        int e = i / D_DIM, d = i - e * D_DIM;
        sWg[e][d] = Wg[d * E_DIM + e];
        sB[e][d] = bexp[i];
    }
    for (int i = tid; i < D_DIM; i += 256) sWt[i] = Wt[i];
    __syncthreads();

    const int warp = tid >> 5, lane = tid & 31;
    const int t = blockIdx.x * 8 + warp;
    const float* xr = x + (size_t)t * D_DIM;
    uint32_t* xh_u = reinterpret_cast<uint32_t*>(g_Xh) + (size_t)t * 256;
    uint32_t* xl_u = reinterpret_cast<uint32_t*>(g_Xl) + (size_t)t * 256;

    float acc[9];
#pragma unroll
    for (int e = 0; e < 9; e++) acc[e] = 0.f;
#pragma unroll
    for (int i = 0; i < 8; i++) {
        int d = 2 * lane + 64 * i;
        float2 xv = *reinterpret_cast<const float2*>(xr + d);
#pragma unroll
        for (int e = 0; e < E_DIM; e++)
            acc[e] = fmaf(xv.y, sWg[e][d + 1], fmaf(xv.x, sWg[e][d], acc[e]));
        acc[8] = fmaf(xv.y, sWt[d + 1], fmaf(xv.x, sWt[d], acc[8]));

        // fused hi/lo fp16 conversion, pair-permuted slot
        __half h0 = __float2half(xv.x), h1 = __float2half(xv.y);
        __half l0 = __float2half(xv.x - __half2float(h0));
        __half l1 = __float2half(xv.y - __half2float(h1));
        int pg = lane + 32 * i;               // global pair index
        int g16 = pg >> 3, p = pg & 7;
        int s = (p < 4) ? 2 * p : 2 * (p - 4) + 1;
        __half2 ph; ph.x = h0; ph.y = h1;
        __half2 pl; pl.x = l0; pl.y = l1;
        xh_u[g16 * 8 + s] = *reinterpret_cast<uint32_t*>(&ph);
        xl_u[g16 * 8 + s] = *reinterpret_cast<uint32_t*>(&pl);
    }
#pragma unroll
    for (int off = 16; off > 0; off >>= 1)
#pragma unroll
        for (int e = 0; e < 9; e++) acc[e] += __shfl_xor_sync(0xffffffffu, acc[e], off);

    float logit[E_DIM];
#pragma unroll
    for (int e = 0; e < E_DIM; e++) logit[e] = acc[e] + bg[e];
    float m = logit[0];
#pragma unroll
    for (int e = 1; e < E_DIM; e++) m = fmaxf(m, logit[e]);
    float p[E_DIM], s = 0.f;
#pragma unroll
    for (int e = 0; e < E_DIM; e++) { p[e] = expf(logit[e] - m); s += p[e]; }
    float inv_s = 1.f / s;
    float thr = (1.f / (1.f + expf(-(acc[8] + bt[0])))) * MAX_THRESHOLD;

    float w[E_DIM], ws = 0.f;
#pragma unroll
    for (int e = 0; e < E_DIM; e++) {
        float a = p[e] * inv_s - thr;
        w[e] = (a >= 0.f) ? a : 0.f;
        ws += w[e];
    }
    if (ws == 0.f) ws = 1.f;
    float inv_ws = 1.f / ws;
    float wn[E_DIM];
#pragma unroll
    for (int e = 0; e < E_DIM; e++) wn[e] = w[e] * inv_ws;   // all lanes have it

    if (lane < E_DIM) {
        float v = 0.f;
#pragma unroll
        for (int e = 0; e < E_DIM; e++) if (lane == e) v = wn[e];
        g_w[t * E_DIM + lane] = v;
        if (v > 0.f) {
            int pos = atomicAdd(&g_cnt[lane], 1);
            g_list[(size_t)lane * T_TOK + pos] = t;
            g_wval[(size_t)lane * T_TOK + pos] = v;
        }
    }

    // fused bias: out[t][n] = sum_e wn[e]*b_e[n], coalesced float4 stores
#pragma unroll
    for (int i = 0; i < 4; i++) {
        int c = lane * 4 + i * 128;
        float4 a4 = make_float4(0.f, 0.f, 0.f, 0.f);
#pragma unroll
        for (int e = 0; e < E_DIM; e++) {
            float4 b4 = *reinterpret_cast<const float4*>(&sB[e][c]);
            a4.x = fmaf(wn[e], b4.x, a4.x);
            a4.y = fmaf(wn[e], b4.y, a4.y);
            a4.z = fmaf(wn[e], b4.z, a4.z);
            a4.w = fmaf(wn[e], b4.w, a4.w);
        }
        *reinterpret_cast<float4*>(out + (size_t)t * D_DIM + c) = a4;
    }
}

// ---------------------------------------------------------------------------
// Kernel 2: W[e][k][n] -> fp16 W'[e][n][k-perm].
// ---------------------------------------------------------------------------
__global__ void wprep_kernel(const float* __restrict__ W)
{
    __shared__ float tile[32][33];
    int e = blockIdx.z;
    int nb = blockIdx.x * 32, kb = blockIdx.y * 32;
    int tx = threadIdx.x, ty = threadIdx.y;   // 32 x 8
    const float* Ws = W + (size_t)e * D_DIM * D_DIM;
#pragma unroll
    for (int j = 0; j < 32; j += 8)
        tile[ty + j][tx] = Ws[(size_t)(kb + ty + j) * D_DIM + nb + tx];
    __syncthreads();
    int grp = tx >> 4, p = (tx & 15) >> 1, lo = tx & 1;
    int s = (p < 4) ? 2 * p : 2 * (p - 4) + 1;
    int kp = kb + grp * 16 + s * 2 + lo;
#pragma unroll
    for (int j = 0; j < 32; j += 8)
        g_Wh[((size_t)e * D_DIM + nb + ty + j) * D_DIM + kp] =
            __float2half(tile[tx][ty + j]);
}

// ---------------------------------------------------------------------------
// Kernel 3: sparse grouped GEMM. Grid (4 N-tiles, 256 M-tiles, 8 experts),
// 256 thr, 2 CTAs/SM. CTA: 128 gathered tokens x 128 cols, K=512 (8 k64
// chunks, double-buffered, one sync/stage). Epilogue: red.v2 w*acc into out.
// ---------------------------------------------------------------------------
#define XCOMP 4096                            // u32 per hi/lo comp
#define XBUF (2 * XCOMP)                      // 8192
#define BBUF 4096                             // 128 rows x 32 u32
#define IDX_OFF 0                             // 128 ints
#define WV_OFF 128                            // 128 floats
#define X_OFF 256                             // 2 buffers
#define B_OFF (X_OFF + 2 * XBUF)              // 16640; 2 buffers
#define SMEM_U32 (B_OFF + 2 * BBUF)           // 24832
#define SMEM_BYTES (SMEM_U32 * 4)             // 99328

__device__ __forceinline__ void issue_stage(
    int tid, uint32_t sm_base, const int* sIdx, int e, int kt, int n0)
{
    const int buf = kt & 1;
#pragma unroll
    for (int i = 0; i < 4; i++) {
        int id = tid + (i << 8);
        int row = id >> 3, ch = id & 7;
        uint32_t wo = (uint32_t)((ch * 4) ^ ((row & 3) * 8));
        uint32_t dst = sm_base + (X_OFF + buf * XBUF + row * 32 + wo) * 4;
        const size_t src = (size_t)sIdx[row] * D_DIM + kt * 64 + ch * 8;
        cp16(dst, g_Xh + src);
        cp16(dst + XCOMP * 4, g_Xl + src);
    }
#pragma unroll
    for (int i = 0; i < 4; i++) {
        int id = tid + (i << 8);
        int row = id >> 3, ch = id & 7;
        uint32_t wo = (uint32_t)((ch * 4) ^ ((row & 3) * 8));
        uint32_t dst = sm_base + (B_OFF + buf * BBUF + row * 32 + wo) * 4;
        cp16(dst, g_Wh + ((size_t)e * D_DIM + n0 + row) * D_DIM + kt * 64 + ch * 8);
    }
    asm volatile("cp.async.commit_group;\n" ::: "memory");
}

__global__ __launch_bounds__(256, 2) void moe_mma_kernel(float* __restrict__ out)
{
    const int e = blockIdx.z;
    const int m0 = blockIdx.y * 128;
    if (m0 >= g_cnt[e]) return;

    extern __shared__ float smem[];
    uint32_t* smemU = reinterpret_cast<uint32_t*>(smem);
    int* sIdx = reinterpret_cast<int*>(smem + IDX_OFF);
    float* sW = smem + WV_OFF;
    const uint32_t sm_base = smem_u32(smem);
    const int tid = threadIdx.x;
    const int lane = tid & 31, wid = tid >> 5;
    const int g = lane >> 2, t4 = lane & 3;
    const int n0 = blockIdx.x * 128;
    const int r0 = wid * 16 + g;
    const int swz = (g & 3) * 8;

    if (tid < 128) {
        sIdx[tid] = g_list[(size_t)e * T_TOK + m0 + tid];
        sW[tid] = g_wval[(size_t)e * T_TOK + m0 + tid];
    }
    __syncthreads();

    float acc[16][4];
#pragma unroll
    for (int nt = 0; nt < 16; nt++)
#pragma unroll
        for (int j = 0; j < 4; j++) acc[nt][j] = 0.f;

    issue_stage(tid, sm_base, sIdx, e, 0, n0);

#pragma unroll 1
    for (int kt = 0; kt < 8; ++kt) {
        asm volatile("cp.async.wait_group 0;\n" ::: "memory");
        __syncthreads();                       // stage kt visible; buf^1 free
        if (kt + 1 < 8) issue_stage(tid, sm_base, sIdx, e, kt + 1, n0);

        const uint32_t* Xb = smemU + X_OFF + (kt & 1) * XBUF;
        const uint32_t* Bb = smemU + B_OFF + (kt & 1) * BBUF;

#pragma unroll
        for (int j = 0; j < 4; j++) {
            uint32_t wo = (uint32_t)((j * 8 + t4 * 2) ^ swz);
            uint2 h0 = *reinterpret_cast<const uint2*>(Xb + r0 * 32 + wo);
            uint2 h1 = *reinterpret_cast<const uint2*>(Xb + (r0 + 8) * 32 + wo);
            uint2 l0 = *reinterpret_cast<const uint2*>(Xb + XCOMP + r0 * 32 + wo);
            uint2 l1 = *reinterpret_cast<const uint2*>(Xb + XCOMP + (r0 + 8) * 32 + wo);
#pragma unroll
            for (int nt = 0; nt < 16; nt++) {
                uint2 b = *reinterpret_cast<const uint2*>(Bb + (nt * 8 + g) * 32 + wo);
                mma_f16(acc[nt], h0.x, h1.x, h0.y, h1.y, b.x, b.y);
                mma_f16(acc[nt], l0.x, l1.x, l0.y, l1.y, b.x, b.y);
            }
        }
    }

    // ---- epilogue: out[t][n] += w * acc (vector red; pads have w==0) ----
#pragma unroll
    for (int rr = 0; rr < 2; rr++) {
        int row_l = r0 + rr * 8;
        float wv = sW[row_l];
        if (wv > 0.f) {
            float* base = out + (size_t)sIdx[row_l] * D_DIM + n0;
#pragma unroll
            for (int nt = 0; nt < 16; nt++) {
                int cl = nt * 8 + 2 * t4;
                red_add_v2(base + cl, wv * acc[nt][rr * 2 + 0],
                                      wv * acc[nt][rr * 2 + 1]);
            }
        }
    }
}

// ---------------------------------------------------------------------------
extern "C" void kernel_launch(void* const* d_in, const int* in_sizes, int n_in,
                              void* d_out, int out_size)
{
    const float* x    = (const float*)d_in[0];
    const float* Wg   = (const float*)d_in[1];
    const float* bg   = (const float*)d_in[2];
    const float* Wt   = (const float*)d_in[3];
    const float* bt   = (const float*)d_in[4];
    const float* Wexp = (const float*)d_in[5];
    const float* bexp = (const float*)d_in[6];
    float* out        = (float*)d_out;

    const int T = in_sizes[0] / D_DIM;          // 32768

    cudaFuncSetAttribute(moe_mma_kernel,
                         cudaFuncAttributeMaxDynamicSharedMemorySize, SMEM_BYTES);

    zero_kernel<<<E_DIM * T_TOK / 4 / 256, 256>>>();
    gating_kernel<<<T / 8, 256>>>(x, Wg, bg, Wt, bt, bexp, out);
    wprep_kernel<<<dim3(16, 16, 8), dim3(32, 8)>>>(Wexp);
    moe_mma_kernel<<<dim3(4, T / 128, E_DIM), 256, SMEM_BYTES>>>(out);
}

// round 14
// speedup vs baseline: 3.8130x; 1.5395x over previous
#include <cuda_runtime.h>
#include <cuda_fp16.h>
#include <cstdint>

// AdaMoeLayer: out[t] = sum_e w[t,e]*(x[t] @ W_e + b_e),  T=32768, D=512, E=8.
// R14: sparse grouped GEMM, SINGLE fp16 product (X and W both fp16-rounded;
// predicted rel_err ~2.9e-4 < 1e-3). Half the MMA work of R13. Bias fused in
// gating; red.global.add.v2.f32 scatter epilogue.

#define D_DIM 512
#define E_DIM 8
#define T_TOK 32768
#define MAX_THRESHOLD 0.25f

// ---- static device scratch ----
__device__ float g_w[T_TOK * E_DIM];                       // gate weights, 1 MB
__device__ int   g_cnt[E_DIM];                             // per-expert counts
__device__ int   g_list[(size_t)E_DIM * T_TOK];            // token ids, 1 MB
__device__ float g_wval[(size_t)E_DIM * T_TOK];            // weights,   1 MB
__device__ __half g_Wh[(size_t)E_DIM * D_DIM * D_DIM];     // fp16 W' [e][n][k-perm]
__device__ __half g_Xh[(size_t)T_TOK * D_DIM];             // fp16 X [t][k-perm]

// ---------------------------------------------------------------------------
__device__ __forceinline__ uint32_t smem_u32(const void* p) {
    uint32_t a;
    asm("{ .reg .u64 t; cvta.to.shared.u64 t, %1; cvt.u32.u64 %0, t; }"
        : "=r"(a) : "l"(p));
    return a;
}
__device__ __forceinline__ void cp16(uint32_t dst, const void* src) {
    asm volatile("cp.async.cg.shared.global [%0], [%1], 16;\n"
                 :: "r"(dst), "l"(__cvta_generic_to_global(src)) : "memory");
}
__device__ __forceinline__ void mma_f16(float* c,
    uint32_t a0, uint32_t a1, uint32_t a2, uint32_t a3,
    uint32_t b0, uint32_t b1)
{
    asm volatile(
        "mma.sync.aligned.m16n8k16.row.col.f32.f16.f16.f32 "
        "{%0,%1,%2,%3}, {%4,%5,%6,%7}, {%8,%9}, {%0,%1,%2,%3};"
        : "+f"(c[0]), "+f"(c[1]), "+f"(c[2]), "+f"(c[3])
        : "r"(a0), "r"(a1), "r"(a2), "r"(a3), "r"(b0), "r"(b1));
}
__device__ __forceinline__ void red_add_v2(float* addr, float v0, float v1) {
    asm volatile("red.global.add.v2.f32 [%0], {%1, %2};"
                 :: "l"(addr), "f"(v0), "f"(v1) : "memory");
}

// ---------------------------------------------------------------------------
// Kernel 0: zero the append state (counts + weight pads).
// ---------------------------------------------------------------------------
__global__ __launch_bounds__(256) void zero_kernel()
{
    int idx = blockIdx.x * 256 + threadIdx.x;
    reinterpret_cast<float4*>(g_wval)[idx] = make_float4(0.f, 0.f, 0.f, 0.f);
    if (blockIdx.x == 0 && threadIdx.x < E_DIM) g_cnt[threadIdx.x] = 0;
}

// ---------------------------------------------------------------------------
// Kernel 1: gating + list append + fused X->fp16 (pair-permuted) + fused
// bias write out[t][n] = sum_e w[t,e]*b_e[n]. One warp per token.
// ---------------------------------------------------------------------------
__global__ __launch_bounds__(256) void gating_kernel(
    const float* __restrict__ x,
    const float* __restrict__ Wg, const float* __restrict__ bg,
    const float* __restrict__ Wt, const float* __restrict__ bt,
    const float* __restrict__ bexp, float* __restrict__ out)
{
    __shared__ float sWg[E_DIM][D_DIM];
    __shared__ float sWt[D_DIM];
    __shared__ float sB[E_DIM][D_DIM];
    const int tid = threadIdx.x;
    for (int i = tid; i < E_DIM * D_DIM; i += 256) {
        int e = i / D_DIM, d = i - e * D_DIM;
        sWg[e][d] = Wg[d * E_DIM + e];
        sB[e][d] = bexp[i];
    }
    for (int i = tid; i < D_DIM; i += 256) sWt[i] = Wt[i];
    __syncthreads();

    const int warp = tid >> 5, lane = tid & 31;
    const int t = blockIdx.x * 8 + warp;
    const float* xr = x + (size_t)t * D_DIM;
    uint32_t* xh_u = reinterpret_cast<uint32_t*>(g_Xh) + (size_t)t * 256;

    float acc[9];
#pragma unroll
    for (int e = 0; e < 9; e++) acc[e] = 0.f;
#pragma unroll
    for (int i = 0; i < 8; i++) {
        int d = 2 * lane + 64 * i;
        float2 xv = *reinterpret_cast<const float2*>(xr + d);
#pragma unroll
        for (int e = 0; e < E_DIM; e++)
            acc[e] = fmaf(xv.y, sWg[e][d + 1], fmaf(xv.x, sWg[e][d], acc[e]));
        acc[8] = fmaf(xv.y, sWt[d + 1], fmaf(xv.x, sWt[d], acc[8]));

        // fused fp16 conversion, pair-permuted slot
        __half h0 = __float2half(xv.x), h1 = __float2half(xv.y);
        int pg = lane + 32 * i;               // global pair index
        int g16 = pg >> 3, p = pg & 7;
        int s = (p < 4) ? 2 * p : 2 * (p - 4) + 1;
        __half2 ph; ph.x = h0; ph.y = h1;
        xh_u[g16 * 8 + s] = *reinterpret_cast<uint32_t*>(&ph);
    }
#pragma unroll
    for (int off = 16; off > 0; off >>= 1)
#pragma unroll
        for (int e = 0; e < 9; e++) acc[e] += __shfl_xor_sync(0xffffffffu, acc[e], off);

    float logit[E_DIM];
#pragma unroll
    for (int e = 0; e < E_DIM; e++) logit[e] = acc[e] + bg[e];
    float m = logit[0];
#pragma unroll
    for (int e = 1; e < E_DIM; e++) m = fmaxf(m, logit[e]);
    float p[E_DIM], s = 0.f;
#pragma unroll
    for (int e = 0; e < E_DIM; e++) { p[e] = expf(logit[e] - m); s += p[e]; }
    float inv_s = 1.f / s;
    float thr = (1.f / (1.f + expf(-(acc[8] + bt[0])))) * MAX_THRESHOLD;

    float w[E_DIM], ws = 0.f;
#pragma unroll
    for (int e = 0; e < E_DIM; e++) {
        float a = p[e] * inv_s - thr;
        w[e] = (a >= 0.f) ? a : 0.f;
        ws += w[e];
    }
    if (ws == 0.f) ws = 1.f;
    float inv_ws = 1.f / ws;
    float wn[E_DIM];
#pragma unroll
    for (int e = 0; e < E_DIM; e++) wn[e] = w[e] * inv_ws;   // all lanes have it

    if (lane < E_DIM) {
        float v = 0.f;
#pragma unroll
        for (int e = 0; e < E_DIM; e++) if (lane == e) v = wn[e];
        g_w[t * E_DIM + lane] = v;
        if (v > 0.f) {
            int pos = atomicAdd(&g_cnt[lane], 1);
            g_list[(size_t)lane * T_TOK + pos] = t;
            g_wval[(size_t)lane * T_TOK + pos] = v;
        }
    }

    // fused bias: out[t][n] = sum_e wn[e]*b_e[n], coalesced float4 stores
#pragma unroll
    for (int i = 0; i < 4; i++) {
        int c = lane * 4 + i * 128;
        float4 a4 = make_float4(0.f, 0.f, 0.f, 0.f);
#pragma unroll
        for (int e = 0; e < E_DIM; e++) {
            float4 b4 = *reinterpret_cast<const float4*>(&sB[e][c]);
            a4.x = fmaf(wn[e], b4.x, a4.x);
            a4.y = fmaf(wn[e], b4.y, a4.y);
            a4.z = fmaf(wn[e], b4.z, a4.z);
            a4.w = fmaf(wn[e], b4.w, a4.w);
        }
        *reinterpret_cast<float4*>(out + (size_t)t * D_DIM + c) = a4;
    }
}

// ---------------------------------------------------------------------------
// Kernel 2: W[e][k][n] -> fp16 W'[e][n][k-perm].
// ---------------------------------------------------------------------------
__global__ void wprep_kernel(const float* __restrict__ W)
{
    __shared__ float tile[32][33];
    int e = blockIdx.z;
    int nb = blockIdx.x * 32, kb = blockIdx.y * 32;
    int tx = threadIdx.x, ty = threadIdx.y;   // 32 x 8
    const float* Ws = W + (size_t)e * D_DIM * D_DIM;
#pragma unroll
    for (int j = 0; j < 32; j += 8)
        tile[ty + j][tx] = Ws[(size_t)(kb + ty + j) * D_DIM + nb + tx];
    __syncthreads();
    int grp = tx >> 4, p = (tx & 15) >> 1, lo = tx & 1;
    int s = (p < 4) ? 2 * p : 2 * (p - 4) + 1;
    int kp = kb + grp * 16 + s * 2 + lo;
#pragma unroll
    for (int j = 0; j < 32; j += 8)
        g_Wh[((size_t)e * D_DIM + nb + ty + j) * D_DIM + kp] =
            __float2half(tile[tx][ty + j]);
}

// ---------------------------------------------------------------------------
// Kernel 3: sparse grouped GEMM. Grid (4 N-tiles, 256 M-tiles, 8 experts),
// 256 thr. CTA: 128 gathered tokens x 128 cols, K=512 (8 k64 chunks,
// double-buffered, one sync/stage). Single fp16 product per fragment.
// Epilogue: red.v2 w*acc into out.
// ---------------------------------------------------------------------------
#define XBUF 4096                             // u32: 128 rows x 32
#define BBUF 4096                             // u32: 128 rows x 32
#define IDX_OFF 0                             // 128 ints
#define WV_OFF 128                            // 128 floats
#define X_OFF 256                             // 2 buffers
#define B_OFF (X_OFF + 2 * XBUF)              // 8448; 2 buffers
#define SMEM_U32 (B_OFF + 2 * BBUF)           // 16640
#define SMEM_BYTES (SMEM_U32 * 4)             // 66560

__device__ __forceinline__ void issue_stage(
    int tid, uint32_t sm_base, const int* sIdx, int e, int kt, int n0)
{
    const int buf = kt & 1;
#pragma unroll
    for (int i = 0; i < 4; i++) {
        int id = tid + (i << 8);
        int row = id >> 3, ch = id & 7;
        uint32_t wo = (uint32_t)((ch * 4) ^ ((row & 3) * 8));
        cp16(sm_base + (X_OFF + buf * XBUF + row * 32 + wo) * 4,
             g_Xh + (size_t)sIdx[row] * D_DIM + kt * 64 + ch * 8);
        cp16(sm_base + (B_OFF + buf * BBUF + row * 32 + wo) * 4,
             g_Wh + ((size_t)e * D_DIM + n0 + row) * D_DIM + kt * 64 + ch * 8);
    }
    asm volatile("cp.async.commit_group;\n" ::: "memory");
}

__global__ __launch_bounds__(256, 2) void moe_mma_kernel(float* __restrict__ out)
{
    const int e = blockIdx.z;
    const int m0 = blockIdx.y * 128;
    if (m0 >= g_cnt[e]) return;

    extern __shared__ float smem[];
    uint32_t* smemU = reinterpret_cast<uint32_t*>(smem);
    int* sIdx = reinterpret_cast<int*>(smem + IDX_OFF);
    float* sW = smem + WV_OFF;
    const uint32_t sm_base = smem_u32(smem);
    const int tid = threadIdx.x;
    const int lane = tid & 31, wid = tid >> 5;
    const int g = lane >> 2, t4 = lane & 3;
    const int n0 = blockIdx.x * 128;
    const int r0 = wid * 16 + g;
    const int swz = (g & 3) * 8;

    if (tid < 128) {
        sIdx[tid] = g_list[(size_t)e * T_TOK + m0 + tid];
        sW[tid] = g_wval[(size_t)e * T_TOK + m0 + tid];
    }
    __syncthreads();

    float acc[16][4];
#pragma unroll
    for (int nt = 0; nt < 16; nt++)
#pragma unroll
        for (int j = 0; j < 4; j++) acc[nt][j] = 0.f;

    issue_stage(tid, sm_base, sIdx, e, 0, n0);

#pragma unroll 1
    for (int kt = 0; kt < 8; ++kt) {
        asm volatile("cp.async.wait_group 0;\n" ::: "memory");
        __syncthreads();                       // stage kt visible; buf^1 free
        if (kt + 1 < 8) issue_stage(tid, sm_base, sIdx, e, kt + 1, n0);

        const uint32_t* Xb = smemU + X_OFF + (kt & 1) * XBUF;
        const uint32_t* Bb = smemU + B_OFF + (kt & 1) * BBUF;

#pragma unroll
        for (int j = 0; j < 4; j++) {
            uint32_t wo = (uint32_t)((j * 8 + t4 * 2) ^ swz);
            uint2 h0 = *reinterpret_cast<const uint2*>(Xb + r0 * 32 + wo);
            uint2 h1 = *reinterpret_cast<const uint2*>(Xb + (r0 + 8) * 32 + wo);
#pragma unroll
            for (int nt = 0; nt < 16; nt++) {
                uint2 b = *reinterpret_cast<const uint2*>(Bb + (nt * 8 + g) * 32 + wo);
                mma_f16(acc[nt], h0.x, h1.x, h0.y, h1.y, b.x, b.y);
            }
        }
    }

    // ---- epilogue: out[t][n] += w * acc (vector red; pads have w==0) ----
#pragma unroll
    for (int rr = 0; rr < 2; rr++) {
        int row_l = r0 + rr * 8;
        float wv = sW[row_l];
        if (wv > 0.f) {
            float* base = out + (size_t)sIdx[row_l] * D_DIM + n0;
#pragma unroll
            for (int nt = 0; nt < 16; nt++) {
                int cl = nt * 8 + 2 * t4;
                red_add_v2(base + cl, wv * acc[nt][rr * 2 + 0],
                                      wv * acc[nt][rr * 2 + 1]);
            }
        }
    }
}

// ---------------------------------------------------------------------------
extern "C" void kernel_launch(void* const* d_in, const int* in_sizes, int n_in,
                              void* d_out, int out_size)
{
    const float* x    = (const float*)d_in[0];
    const float* Wg   = (const float*)d_in[1];
    const float* bg   = (const float*)d_in[2];
    const float* Wt   = (const float*)d_in[3];
    const float* bt   = (const float*)d_in[4];
    const float* Wexp = (const float*)d_in[5];
    const float* bexp = (const float*)d_in[6];
    float* out        = (float*)d_out;

    const int T = in_sizes[0] / D_DIM;          // 32768

    cudaFuncSetAttribute(moe_mma_kernel,
                         cudaFuncAttributeMaxDynamicSharedMemorySize, SMEM_BYTES);

    zero_kernel<<<E_DIM * T_TOK / 4 / 256, 256>>>();
    gating_kernel<<<T / 8, 256>>>(x, Wg, bg, Wt, bt, bexp, out);
    wprep_kernel<<<dim3(16, 16, 8), dim3(32, 8)>>>(Wexp);
    moe_mma_kernel<<<dim3(4, T / 128, E_DIM), 256, SMEM_BYTES>>>(out);
}

// round 15
// speedup vs baseline: 3.8139x; 1.0002x over previous
#include <cuda_runtime.h>
#include <cuda_fp16.h>
#include <cstdint>

// AdaMoeLayer: out[t] = sum_e w[t,e]*(x[t] @ W_e + b_e),  T=32768, D=512, E=8.
// R15: sparse grouped GEMM, single fp16 product, 3-stage cp.async ring
// (depth-2 prefetch), pad masking at tile load (no zero kernel), bias fused
// in gating, red.global.add.v2.f32 scatter epilogue.

#define D_DIM 512
#define E_DIM 8
#define T_TOK 32768
#define MAX_THRESHOLD 0.25f

// ---- static device scratch ----
__device__ float g_w[T_TOK * E_DIM];                       // gate weights, 1 MB
__device__ int   g_cnt[E_DIM];                             // per-expert counts
__device__ int   g_list[(size_t)E_DIM * T_TOK];            // token ids, 1 MB
__device__ float g_wval[(size_t)E_DIM * T_TOK];            // weights,   1 MB
__device__ __half g_Wh[(size_t)E_DIM * D_DIM * D_DIM];     // fp16 W' [e][n][k-perm]
__device__ __half g_Xh[(size_t)T_TOK * D_DIM];             // fp16 X [t][k-perm]

// ---------------------------------------------------------------------------
__device__ __forceinline__ uint32_t smem_u32(const void* p) {
    uint32_t a;
    asm("{ .reg .u64 t; cvta.to.shared.u64 t, %1; cvt.u32.u64 %0, t; }"
        : "=r"(a) : "l"(p));
    return a;
}
__device__ __forceinline__ void cp16(uint32_t dst, const void* src) {
    asm volatile("cp.async.cg.shared.global [%0], [%1], 16;\n"
                 :: "r"(dst), "l"(__cvta_generic_to_global(src)) : "memory");
}
__device__ __forceinline__ void mma_f16(float* c,
    uint32_t a0, uint32_t a1, uint32_t a2, uint32_t a3,
    uint32_t b0, uint32_t b1)
{
    asm volatile(
        "mma.sync.aligned.m16n8k16.row.col.f32.f16.f16.f32 "
        "{%0,%1,%2,%3}, {%4,%5,%6,%7}, {%8,%9}, {%0,%1,%2,%3};"
        : "+f"(c[0]), "+f"(c[1]), "+f"(c[2]), "+f"(c[3])
        : "r"(a0), "r"(a1), "r"(a2), "r"(a3), "r"(b0), "r"(b1));
}
__device__ __forceinline__ void red_add_v2(float* addr, float v0, float v1) {
    asm volatile("red.global.add.v2.f32 [%0], {%1, %2};"
                 :: "l"(addr), "f"(v0), "f"(v1) : "memory");
}

// ---------------------------------------------------------------------------
// Kernel 1: W[e][k][n] -> fp16 W'[e][n][k-perm].  Also zeroes g_cnt
// (stream-ordered before gating).
// ---------------------------------------------------------------------------
__global__ void wprep_kernel(const float* __restrict__ W)
{
    __shared__ float tile[32][33];
    int e = blockIdx.z;
    int nb = blockIdx.x * 32, kb = blockIdx.y * 32;
    int tx = threadIdx.x, ty = threadIdx.y;   // 32 x 8
    if (blockIdx.x == 0 && blockIdx.y == 0 && blockIdx.z == 0 &&
        ty == 0 && tx < E_DIM)
        g_cnt[tx] = 0;
    const float* Ws = W + (size_t)e * D_DIM * D_DIM;
#pragma unroll
    for (int j = 0; j < 32; j += 8)
        tile[ty + j][tx] = Ws[(size_t)(kb + ty + j) * D_DIM + nb + tx];
    __syncthreads();
    int grp = tx >> 4, p = (tx & 15) >> 1, lo = tx & 1;
    int s = (p < 4) ? 2 * p : 2 * (p - 4) + 1;
    int kp = kb + grp * 16 + s * 2 + lo;
#pragma unroll
    for (int j = 0; j < 32; j += 8)
        g_Wh[((size_t)e * D_DIM + nb + ty + j) * D_DIM + kp] =
            __float2half(tile[tx][ty + j]);
}

// ---------------------------------------------------------------------------
// Kernel 2: gating + list append + fused X->fp16 (pair-permuted) + fused
// bias write out[t][n] = sum_e w[t,e]*b_e[n]. One warp per token.
// ---------------------------------------------------------------------------
__global__ __launch_bounds__(256) void gating_kernel(
    const float* __restrict__ x,
    const float* __restrict__ Wg, const float* __restrict__ bg,
    const float* __restrict__ Wt, const float* __restrict__ bt,
    const float* __restrict__ bexp, float* __restrict__ out)
{
    __shared__ float sWg[E_DIM][D_DIM];
    __shared__ float sWt[D_DIM];
    __shared__ float sB[E_DIM][D_DIM];
    const int tid = threadIdx.x;
    for (int i = tid; i < E_DIM * D_DIM; i += 256) {
        int e = i / D_DIM, d = i - e * D_DIM;
        sWg[e][d] = Wg[d * E_DIM + e];
        sB[e][d] = bexp[i];
    }
    for (int i = tid; i < D_DIM; i += 256) sWt[i] = Wt[i];
    __syncthreads();

    const int warp = tid >> 5, lane = tid & 31;
    const int t = blockIdx.x * 8 + warp;
    const float* xr = x + (size_t)t * D_DIM;
    uint32_t* xh_u = reinterpret_cast<uint32_t*>(g_Xh) + (size_t)t * 256;

    float acc[9];
#pragma unroll
    for (int e = 0; e < 9; e++) acc[e] = 0.f;
#pragma unroll
    for (int i = 0; i < 8; i++) {
        int d = 2 * lane + 64 * i;
        float2 xv = *reinterpret_cast<const float2*>(xr + d);
#pragma unroll
        for (int e = 0; e < E_DIM; e++)
            acc[e] = fmaf(xv.y, sWg[e][d + 1], fmaf(xv.x, sWg[e][d], acc[e]));
        acc[8] = fmaf(xv.y, sWt[d + 1], fmaf(xv.x, sWt[d], acc[8]));

        __half h0 = __float2half(xv.x), h1 = __float2half(xv.y);
        int pg = lane + 32 * i;               // global pair index
        int g16 = pg >> 3, p = pg & 7;
        int s = (p < 4) ? 2 * p : 2 * (p - 4) + 1;
        __half2 ph; ph.x = h0; ph.y = h1;
        xh_u[g16 * 8 + s] = *reinterpret_cast<uint32_t*>(&ph);
    }
#pragma unroll
    for (int off = 16; off > 0; off >>= 1)
#pragma unroll
        for (int e = 0; e < 9; e++) acc[e] += __shfl_xor_sync(0xffffffffu, acc[e], off);

    float logit[E_DIM];
#pragma unroll
    for (int e = 0; e < E_DIM; e++) logit[e] = acc[e] + bg[e];
    float m = logit[0];
#pragma unroll
    for (int e = 1; e < E_DIM; e++) m = fmaxf(m, logit[e]);
    float p[E_DIM], s = 0.f;
#pragma unroll
    for (int e = 0; e < E_DIM; e++) { p[e] = expf(logit[e] - m); s += p[e]; }
    float inv_s = 1.f / s;
    float thr = (1.f / (1.f + expf(-(acc[8] + bt[0])))) * MAX_THRESHOLD;

    float w[E_DIM], ws = 0.f;
#pragma unroll
    for (int e = 0; e < E_DIM; e++) {
        float a = p[e] * inv_s - thr;
        w[e] = (a >= 0.f) ? a : 0.f;
        ws += w[e];
    }
    if (ws == 0.f) ws = 1.f;
    float inv_ws = 1.f / ws;
    float wn[E_DIM];
#pragma unroll
    for (int e = 0; e < E_DIM; e++) wn[e] = w[e] * inv_ws;

    if (lane < E_DIM) {
        float v = 0.f;
#pragma unroll
        for (int e = 0; e < E_DIM; e++) if (lane == e) v = wn[e];
        g_w[t * E_DIM + lane] = v;
        if (v > 0.f) {
            int pos = atomicAdd(&g_cnt[lane], 1);
            g_list[(size_t)lane * T_TOK + pos] = t;
            g_wval[(size_t)lane * T_TOK + pos] = v;
        }
    }

    // fused bias: out[t][n] = sum_e wn[e]*b_e[n]
#pragma unroll
    for (int i = 0; i < 4; i++) {
        int c = lane * 4 + i * 128;
        float4 a4 = make_float4(0.f, 0.f, 0.f, 0.f);
#pragma unroll
        for (int e = 0; e < E_DIM; e++) {
            float4 b4 = *reinterpret_cast<const float4*>(&sB[e][c]);
            a4.x = fmaf(wn[e], b4.x, a4.x);
            a4.y = fmaf(wn[e], b4.y, a4.y);
            a4.z = fmaf(wn[e], b4.z, a4.z);
            a4.w = fmaf(wn[e], b4.w, a4.w);
        }
        *reinterpret_cast<float4*>(out + (size_t)t * D_DIM + c) = a4;
    }
}

// ---------------------------------------------------------------------------
// Kernel 3: sparse grouped GEMM. Grid (4 N-tiles, 256 M-tiles, 8 experts),
// 256 thr, 2 CTAs/SM. CTA: 128 gathered tokens x 128 cols, K=512 in 8 k64
// chunks, 3-stage cp.async ring (depth-2 prefetch), one sync/stage.
// Pad rows masked at tile load. Epilogue: red.v2 w*acc into out.
// ---------------------------------------------------------------------------
#define XBUF 4096                             // u32: 128 rows x 32
#define BBUF 4096                             // u32: 128 rows x 32
#define IDX_OFF 0                             // 128 ints
#define WV_OFF 128                            // 128 floats
#define X_OFF 256                             // 3 buffers
#define B_OFF (X_OFF + 3 * XBUF)              // 12544; 3 buffers
#define SMEM_U32 (B_OFF + 3 * BBUF)           // 24832
#define SMEM_BYTES (SMEM_U32 * 4)             // 99328

__device__ __forceinline__ void issue_stage(
    int tid, uint32_t sm_base, const int* sIdx, int e, int kt, int n0)
{
    const int buf = kt % 3;
#pragma unroll
    for (int i = 0; i < 4; i++) {
        int id = tid + (i << 8);
        int row = id >> 3, ch = id & 7;
        uint32_t wo = (uint32_t)((ch * 4) ^ ((row & 3) * 8));
        cp16(sm_base + (X_OFF + buf * XBUF + row * 32 + wo) * 4,
             g_Xh + (size_t)sIdx[row] * D_DIM + kt * 64 + ch * 8);
        cp16(sm_base + (B_OFF + buf * BBUF + row * 32 + wo) * 4,
             g_Wh + ((size_t)e * D_DIM + n0 + row) * D_DIM + kt * 64 + ch * 8);
    }
    asm volatile("cp.async.commit_group;\n" ::: "memory");
}

__global__ __launch_bounds__(256, 2) void moe_mma_kernel(float* __restrict__ out)
{
    const int e = blockIdx.z;
    const int m0 = blockIdx.y * 128;
    const int cnt = g_cnt[e];
    if (m0 >= cnt) return;

    extern __shared__ float smem[];
    uint32_t* smemU = reinterpret_cast<uint32_t*>(smem);
    int* sIdx = reinterpret_cast<int*>(smem + IDX_OFF);
    float* sW = smem + WV_OFF;
    const uint32_t sm_base = smem_u32(smem);
    const int tid = threadIdx.x;
    const int lane = tid & 31, wid = tid >> 5;
    const int g = lane >> 2, t4 = lane & 3;
    const int n0 = blockIdx.x * 128;
    const int r0 = wid * 16 + g;
    const int swz = (g & 3) * 8;

    if (tid < 128) {
        int idx = m0 + tid;
        if (idx < cnt) {
            sIdx[tid] = g_list[(size_t)e * T_TOK + idx];
            sW[tid]   = g_wval[(size_t)e * T_TOK + idx];
        } else {
            sIdx[tid] = 0;
            sW[tid]   = 0.f;
        }
    }
    __syncthreads();

    float acc[16][4];
#pragma unroll
    for (int nt = 0; nt < 16; nt++)
#pragma unroll
        for (int j = 0; j < 4; j++) acc[nt][j] = 0.f;

    issue_stage(tid, sm_base, sIdx, e, 0, n0);
    issue_stage(tid, sm_base, sIdx, e, 1, n0);

#pragma unroll 1
    for (int kt = 0; kt < 8; ++kt) {
        if (kt + 2 < 8) asm volatile("cp.async.wait_group 1;\n" ::: "memory");
        else if (kt + 1 < 8) asm volatile("cp.async.wait_group 1;\n" ::: "memory");
        else asm volatile("cp.async.wait_group 0;\n" ::: "memory");
        __syncthreads();                       // stage kt ready; buf (kt+2)%3 free
        if (kt + 2 < 8) issue_stage(tid, sm_base, sIdx, e, kt + 2, n0);

        const uint32_t* Xb = smemU + X_OFF + (kt % 3) * XBUF;
        const uint32_t* Bb = smemU + B_OFF + (kt % 3) * BBUF;

#pragma unroll
        for (int j = 0; j < 4; j++) {
            uint32_t wo = (uint32_t)((j * 8 + t4 * 2) ^ swz);
            uint2 h0 = *reinterpret_cast<const uint2*>(Xb + r0 * 32 + wo);
            uint2 h1 = *reinterpret_cast<const uint2*>(Xb + (r0 + 8) * 32 + wo);
#pragma unroll
            for (int nt = 0; nt < 16; nt++) {
                uint2 b = *reinterpret_cast<const uint2*>(Bb + (nt * 8 + g) * 32 + wo);
                mma_f16(acc[nt], h0.x, h1.x, h0.y, h1.y, b.x, b.y);
            }
        }
    }

    // ---- epilogue: out[t][n] += w * acc (vector red; pads have w==0) ----
#pragma unroll
    for (int rr = 0; rr < 2; rr++) {
        int row_l = r0 + rr * 8;
        float wv = sW[row_l];
        if (wv > 0.f) {
            float* base = out + (size_t)sIdx[row_l] * D_DIM + n0;
#pragma unroll
            for (int nt = 0; nt < 16; nt++) {
                int cl = nt * 8 + 2 * t4;
                red_add_v2(base + cl, wv * acc[nt][rr * 2 + 0],
                                      wv * acc[nt][rr * 2 + 1]);
            }
        }
    }
}

// ---------------------------------------------------------------------------
extern "C" void kernel_launch(void* const* d_in, const int* in_sizes, int n_in,
                              void* d_out, int out_size)
{
    const float* x    = (const float*)d_in[0];
    const float* Wg   = (const float*)d_in[1];
    const float* bg   = (const float*)d_in[2];
    const float* Wt   = (const float*)d_in[3];
    const float* bt   = (const float*)d_in[4];
    const float* Wexp = (const float*)d_in[5];
    const float* bexp = (const float*)d_in[6];
    float* out        = (float*)d_out;

    const int T = in_sizes[0] / D_DIM;          // 32768

    cudaFuncSetAttribute(moe_mma_kernel,
                         cudaFuncAttributeMaxDynamicSharedMemorySize, SMEM_BYTES);

    wprep_kernel<<<dim3(16, 16, 8), dim3(32, 8)>>>(Wexp);   // also zeroes g_cnt
    gating_kernel<<<T / 8, 256>>>(x, Wg, bg, Wt, bt, bexp, out);
    moe_mma_kernel<<<dim3(4, T / 128, E_DIM), 256, SMEM_BYTES>>>(out);
}